// round 8
// baseline (speedup 1.0000x reference)
#include <cuda_runtime.h>
#include <cuda_fp16.h>
#include <cstdint>

#define BT_ 16384
#define T_ 2048
#define B_ 8
#define H_ 1024
#define I_ 2048
#define N_SSM 16
#define R_ 64
#define M_MLP 2816

// ------------------------- scratch (device globals) --------------------------
__device__ __half g_h[BT_ * H_];        // rmsnorm out (half, GEMM A)
__device__ __half g_proj_h[BT_ * 4096]; // in_proj out / MLP gate out (half)
__device__ __half g_xi[BT_ * I_];       // conv+silu out (half)
__device__ float  g_sp[BT_ * 96];       // x_proj out fp32 (scan B/C)
__device__ __half g_sp_h[BT_ * 96];     // x_proj out half (dt GEMM A)
__device__ float  g_dt[BT_ * I_];       // softplus dt (fp32, scan)
__device__ __half g_y_h[BT_ * I_];      // gated y half (out_proj A)
__device__ float  g_x2[BT_ * H_];       // mixer residual out
__device__ __half g_act[BT_ * M_MLP];   // silu(gate)*up (half, down A)
__device__ __half g_w_in[4096 * H_];
__device__ __half g_w_xp[96 * I_];
__device__ __half g_w_dt[I_ * R_];
__device__ __half g_w_out[H_ * I_];
__device__ __half g_w_gate[M_MLP * H_];
__device__ __half g_w_up[M_MLP * H_];
__device__ __half g_w_down[H_ * M_MLP];

__device__ __forceinline__ float siluf(float g) {
    return g * (1.0f / (1.0f + __expf(-g)));
}
__device__ __forceinline__ uint32_t smem_u32(const void* p) {
    return (uint32_t)__cvta_generic_to_shared(p);
}
__device__ __forceinline__ void cp4(uint32_t dst, const void* src) {
    asm volatile("cp.async.ca.shared.global [%0], [%1], 4;" ::"r"(dst), "l"(src));
}
#define CP_COMMIT() asm volatile("cp.async.commit_group;" ::: "memory")
#define CP_WAIT2() asm volatile("cp.async.wait_group 2;" ::: "memory")

// mma.sync m16n8k16 f16 -> f32 accum
#define MMA16(d, a0, a1, a2, a3, b0, b1)                                       \
    asm volatile(                                                              \
        "mma.sync.aligned.m16n8k16.row.col.f32.f16.f16.f32 "                   \
        "{%0,%1,%2,%3},{%4,%5,%6,%7},{%8,%9},{%0,%1,%2,%3};"                   \
        : "+f"((d)[0]), "+f"((d)[1]), "+f"((d)[2]), "+f"((d)[3])               \
        : "r"(a0), "r"(a1), "r"(a2), "r"(a3), "r"(b0), "r"(b1))

// ------------------------- fp16 mma.sync GEMM (R5 config) --------------------
// C[M,N] = A[M,K] @ W[N,K]^T, A/W half K-major. BM=BN=128, BK=32, 4 stages,
// 8 warps (2m x 4n), warp tile 64x32, 2 CTAs/SM.
// Smem row = 32 halfs (64B), k-pair-permuted: pair kp at pair-pos
// pp = 4*(kp&3) + ((kp>>2)&1) + 2*(kp>>3); one LDS.128 at (row, qc*16B) =
// the m16n8k16 fragment k-slices for both k-steps.
// mode 0: C fp32 (if C) and/or Ch half (if Ch); 1: softplus(acc+aux[n])->C;
// 2: acc+aux[m*N+n]->C; 3: half(acc*silu(auxh[m*N+n]))->Ch
#define STAGES 4
#define STG_U32 4096  // A 2048 + B 2048 (u32 units)
#define GEMM_SMEM (STAGES * STG_U32 * 4)  // 64 KB

__global__ __launch_bounds__(256, 2) void hgemm(
    const __half* __restrict__ A, int lda, const __half* __restrict__ W,
    const float* __restrict__ aux, const __half* __restrict__ auxh,
    float* __restrict__ C, __half* __restrict__ Ch, int N, int K, int mode,
    int n_valid) {
    extern __shared__ uint32_t sm[];
    const int tid = threadIdx.x;
    const int lane = tid & 31, wid = tid >> 5;
    const int wm = wid & 1, wn = wid >> 1;
    const int qr = lane >> 2, qc = lane & 3;
    const int bm = blockIdx.y * 128, bn = blockIdx.x * 128;
    const int nk = K >> 5;

    float acc[4][4][4];
#pragma unroll
    for (int mi = 0; mi < 4; mi++)
#pragma unroll
        for (int ni = 0; ni < 4; ni++)
#pragma unroll
            for (int q = 0; q < 4; q++) acc[mi][ni][q] = 0.f;

    auto load_stage = [&](int s, int kt) {
        uint32_t* sA = sm + s * STG_U32;
        uint32_t* sB = sA + 2048;
#pragma unroll
        for (int i = 0; i < 8; i++) {
            int w = tid + i * 256;
            int row = w >> 4, kp = w & 15;
            int pp = 4 * (kp & 3) + ((kp >> 2) & 1) + 2 * (kp >> 3);
            cp4(smem_u32(sA + row * 16 + pp),
                A + (size_t)(bm + row) * lda + kt * 32 + 2 * kp);
        }
#pragma unroll
        for (int i = 0; i < 8; i++) {
            int w = tid + i * 256;
            int row = w >> 4, kp = w & 15;
            int pp = 4 * (kp & 3) + ((kp >> 2) & 1) + 2 * (kp >> 3);
            if (bn + row < n_valid)
                cp4(smem_u32(sB + row * 16 + pp),
                    W + (size_t)(bn + row) * (size_t)K + kt * 32 + 2 * kp);
        }
    };

    for (int s = 0; s < STAGES - 1; s++) {
        if (s < nk) load_stage(s, s);
        CP_COMMIT();
    }

    for (int kt = 0; kt < nk; kt++) {
        CP_WAIT2();
        __syncthreads();
        int pf = kt + STAGES - 1;
        if (pf < nk) load_stage(pf & 3, pf);
        CP_COMMIT();

        const uint32_t* As = sm + (kt & 3) * STG_U32;
        const uint32_t* Bs = As + 2048;
        uint4 alo[4], ahi[4], bb[4];
#pragma unroll
        for (int mi = 0; mi < 4; mi++) {
            int r = wm * 64 + mi * 16 + qr;
            alo[mi] = *(const uint4*)(As + r * 16 + qc * 4);
            ahi[mi] = *(const uint4*)(As + (r + 8) * 16 + qc * 4);
        }
#pragma unroll
        for (int ni = 0; ni < 4; ni++) {
            int r = wn * 32 + ni * 8 + qr;
            bb[ni] = *(const uint4*)(Bs + r * 16 + qc * 4);
        }
#pragma unroll
        for (int mi = 0; mi < 4; mi++)
#pragma unroll
            for (int ni = 0; ni < 4; ni++) {
                MMA16(acc[mi][ni], alo[mi].x, ahi[mi].x, alo[mi].y, ahi[mi].y,
                      bb[ni].x, bb[ni].y);
                MMA16(acc[mi][ni], alo[mi].z, ahi[mi].z, alo[mi].w, ahi[mi].w,
                      bb[ni].z, bb[ni].w);
            }
    }

    // epilogue: thread holds (r0,c0),(r0,c0+1),(r0+8,c0),(r0+8,c0+1) per tile
#pragma unroll
    for (int mi = 0; mi < 4; mi++) {
#pragma unroll
        for (int ni = 0; ni < 4; ni++) {
            int r0 = bm + wm * 64 + mi * 16 + qr;
            int c0 = bn + wn * 32 + ni * 8 + 2 * qc;
            if (c0 >= n_valid) continue;
            float v00 = acc[mi][ni][0], v01 = acc[mi][ni][1];
            float v10 = acc[mi][ni][2], v11 = acc[mi][ni][3];
            size_t g0 = (size_t)r0 * (size_t)N + c0;
            size_t g1 = g0 + (size_t)8 * N;
            if (mode == 1) {
                float b0 = __ldg(aux + c0), b1 = __ldg(aux + c0 + 1);
                float z;
                z = v00 + b0; v00 = fmaxf(z, 0.f) + log1pf(__expf(-fabsf(z)));
                z = v01 + b1; v01 = fmaxf(z, 0.f) + log1pf(__expf(-fabsf(z)));
                z = v10 + b0; v10 = fmaxf(z, 0.f) + log1pf(__expf(-fabsf(z)));
                z = v11 + b1; v11 = fmaxf(z, 0.f) + log1pf(__expf(-fabsf(z)));
                *(float2*)(C + g0) = make_float2(v00, v01);
                *(float2*)(C + g1) = make_float2(v10, v11);
            } else if (mode == 2) {
                float2 r0v = *(const float2*)(aux + g0);
                float2 r1v = *(const float2*)(aux + g1);
                *(float2*)(C + g0) = make_float2(v00 + r0v.x, v01 + r0v.y);
                *(float2*)(C + g1) = make_float2(v10 + r1v.x, v11 + r1v.y);
            } else if (mode == 3) {
                __half2 a0v = *(const __half2*)(auxh + g0);
                __half2 a1v = *(const __half2*)(auxh + g1);
                *(__half2*)(Ch + g0) = __floats2half2_rn(
                    v00 * siluf(__low2float(a0v)), v01 * siluf(__high2float(a0v)));
                *(__half2*)(Ch + g1) = __floats2half2_rn(
                    v10 * siluf(__low2float(a1v)), v11 * siluf(__high2float(a1v)));
            } else {
                if (C != nullptr) {
                    *(float2*)(C + g0) = make_float2(v00, v01);
                    *(float2*)(C + g1) = make_float2(v10, v11);
                }
                if (Ch != nullptr) {
                    *(__half2*)(Ch + g0) = __floats2half2_rn(v00, v01);
                    *(__half2*)(Ch + g1) = __floats2half2_rn(v10, v11);
                }
            }
        }
    }
}

// --------------------------- fp32 -> fp16 convert ----------------------------
__global__ void to_half_kernel(const float* __restrict__ src,
                               __half* __restrict__ dst, int n4) {
    int i = blockIdx.x * 256 + threadIdx.x;
    if (i < n4) {
        float4 v = ((const float4*)src)[i];
        __half2 h0 = __floats2half2_rn(v.x, v.y);
        __half2 h1 = __floats2half2_rn(v.z, v.w);
        uint2 o;
        o.x = *(uint32_t*)&h0;
        o.y = *(uint32_t*)&h1;
        ((uint2*)dst)[i] = o;
    }
}

// ------------------------------- rmsnorm (-> half) ---------------------------
__global__ void rmsnorm_kernel(const float* __restrict__ x,
                               const float* __restrict__ w,
                               __half* __restrict__ out) {
    int row = blockIdx.x;
    int t = threadIdx.x;
    const float4* xr = (const float4*)(x + (size_t)row * H_);
    float4 v = xr[t];
    float ss = v.x * v.x + v.y * v.y + v.z * v.z + v.w * v.w;
#pragma unroll
    for (int o = 16; o > 0; o >>= 1) ss += __shfl_down_sync(0xffffffffu, ss, o);
    __shared__ float red[8];
    if ((t & 31) == 0) red[t >> 5] = ss;
    __syncthreads();
    float tot = red[0] + red[1] + red[2] + red[3] + red[4] + red[5] + red[6] + red[7];
    float scale = rsqrtf(tot * (1.0f / (float)H_) + 1e-5f);
    float4 wv = ((const float4*)w)[t];
    __half2 h0 = __floats2half2_rn(v.x * scale * wv.x, v.y * scale * wv.y);
    __half2 h1 = __floats2half2_rn(v.z * scale * wv.z, v.w * scale * wv.w);
    uint2 o;
    o.x = *(uint32_t*)&h0;
    o.y = *(uint32_t*)&h1;
    ((uint2*)(out + (size_t)row * H_))[t] = o;
}

// ---------------- causal depthwise conv + silu (half in, half out) -----------
__global__ void conv_silu_kernel(const __half* __restrict__ proj,
                                 const float* __restrict__ cw,
                                 const float* __restrict__ cb,
                                 __half* __restrict__ xi) {
    int idx = blockIdx.x * blockDim.x + threadIdx.x;
    int i4 = idx & 511;
    int bt = idx >> 9;
    int t = bt & (T_ - 1);
    const float4* cwv = (const float4*)cw;
    float w[4][4];
#pragma unroll
    for (int c = 0; c < 4; c++) {
        float4 tmp = cwv[i4 * 4 + c];
        w[c][0] = tmp.x; w[c][1] = tmp.y; w[c][2] = tmp.z; w[c][3] = tmp.w;
    }
    float4 cbv = ((const float4*)cb)[i4];
    float acc[4] = {cbv.x, cbv.y, cbv.z, cbv.w};
    const __half* base = proj + (size_t)bt * 4096 + i4 * 4;
#pragma unroll
    for (int k = 0; k < 4; ++k) {
        int back = 3 - k;
        if (t >= back) {
            uint2 pr = *(const uint2*)(base - (size_t)back * 4096);
            __half2 p0 = *(__half2*)&pr.x;
            __half2 p1 = *(__half2*)&pr.y;
            acc[0] += __low2float(p0) * w[0][k];
            acc[1] += __high2float(p0) * w[1][k];
            acc[2] += __low2float(p1) * w[2][k];
            acc[3] += __high2float(p1) * w[3][k];
        }
    }
    __half2 h0 = __floats2half2_rn(siluf(acc[0]), siluf(acc[1]));
    __half2 h1 = __floats2half2_rn(siluf(acc[2]), siluf(acc[3]));
    uint2 o;
    o.x = *(uint32_t*)&h0;
    o.y = *(uint32_t*)&h1;
    ((uint2*)xi)[idx] = o;
}

// --------------- selective scan + fused ypost (y_h out, half) ----------------
__global__ __launch_bounds__(256) void scan_kernel(
    const float* __restrict__ dt, const float* __restrict__ sp,
    const __half* __restrict__ xi, const float* __restrict__ A_log,
    const __half* __restrict__ proj, const float* __restrict__ D,
    __half* __restrict__ yh) {
    __shared__ float sBC[64][32];
    int tid = threadIdx.x;
    int warp = tid >> 5, lane = tid & 31;
    int half_ = lane >> 4, n = lane & 15;
    int chan = blockIdx.x * 16 + warp * 2 + half_;
    int b = chan >> 11;
    int i = chan & (I_ - 1);
    float A = -__expf(__ldg(A_log + i * N_SSM + n));
    float Dv = __ldg(D + i);
    size_t rowoff = (size_t)b * T_ * I_ + i;
    size_t spoff = (size_t)b * T_ * 96;
    size_t poff = (size_t)b * T_ * 4096 + I_ + i;
    float s = 0.f;

    for (int t0 = 0; t0 < T_; t0 += 64) {
        __syncthreads();
#pragma unroll
        for (int q = tid; q < 512; q += 256) {
            int r = q >> 3, c = (q & 7) << 2;
            *(float4*)&sBC[r][c] =
                *(const float4*)(sp + spoff + (size_t)(t0 + r) * 96 + 64 + c);
        }
        __syncthreads();
        size_t off = rowoff + (size_t)t0 * I_;
        size_t po = poff + (size_t)t0 * 4096;
        for (int tl = 0; tl < 64; ++tl, off += I_, po += 4096) {
            float dtv = __ldg(dt + off);
            float xv = __half2float(__ldg(xi + off));
            float dA = __expf(dtv * A);
            s = fmaf(dA, s, dtv * xv * sBC[tl][n]);
            float yv = s * sBC[tl][16 + n];
            yv += __shfl_down_sync(0xffffffffu, yv, 8, 16);
            yv += __shfl_down_sync(0xffffffffu, yv, 4, 16);
            yv += __shfl_down_sync(0xffffffffu, yv, 2, 16);
            yv += __shfl_down_sync(0xffffffffu, yv, 1, 16);
            if (n == 0) {
                float g = __half2float(__ldg(proj + po));
                yh[off] = __float2half_rn((yv + xv * Dv) * siluf(g));
            }
        }
    }
}

// ------------------------------- launch --------------------------------------
extern "C" void kernel_launch(void* const* d_in, const int* in_sizes, int n_in,
                              void* d_out, int out_size) {
    const float* x            = (const float*)d_in[0];
    const float* mixer_norm_w = (const float*)d_in[1];
    const float* in_proj_w    = (const float*)d_in[2];
    const float* conv_w       = (const float*)d_in[3];
    const float* conv_b       = (const float*)d_in[4];
    const float* x_proj_w     = (const float*)d_in[5];
    const float* dt_proj_w    = (const float*)d_in[6];
    const float* dt_proj_b    = (const float*)d_in[7];
    const float* A_log        = (const float*)d_in[8];
    const float* Dv           = (const float*)d_in[9];
    const float* out_proj_w   = (const float*)d_in[10];
    const float* mlp_norm_w   = (const float*)d_in[11];
    const float* gate_w       = (const float*)d_in[12];
    const float* up_w         = (const float*)d_in[13];
    const float* down_w       = (const float*)d_in[14];
    float* out = (float*)d_out;

    __half *h, *proj_h, *xi, *sp_h, *y_h, *act;
    float *sp, *dt, *x2;
    __half *w_in, *w_xp, *w_dt, *w_out, *w_gate, *w_up, *w_down;
    cudaGetSymbolAddress((void**)&h, g_h);
    cudaGetSymbolAddress((void**)&proj_h, g_proj_h);
    cudaGetSymbolAddress((void**)&xi, g_xi);
    cudaGetSymbolAddress((void**)&sp, g_sp);
    cudaGetSymbolAddress((void**)&sp_h, g_sp_h);
    cudaGetSymbolAddress((void**)&dt, g_dt);
    cudaGetSymbolAddress((void**)&y_h, g_y_h);
    cudaGetSymbolAddress((void**)&x2, g_x2);
    cudaGetSymbolAddress((void**)&act, g_act);
    cudaGetSymbolAddress((void**)&w_in, g_w_in);
    cudaGetSymbolAddress((void**)&w_xp, g_w_xp);
    cudaGetSymbolAddress((void**)&w_dt, g_w_dt);
    cudaGetSymbolAddress((void**)&w_out, g_w_out);
    cudaGetSymbolAddress((void**)&w_gate, g_w_gate);
    cudaGetSymbolAddress((void**)&w_up, g_w_up);
    cudaGetSymbolAddress((void**)&w_down, g_w_down);

    cudaFuncSetAttribute(hgemm, cudaFuncAttributeMaxDynamicSharedMemorySize,
                         GEMM_SMEM);

    to_half_kernel<<<4096, 256>>>(in_proj_w, w_in, 4096 * H_ / 4);
    to_half_kernel<<<192, 256>>>(x_proj_w, w_xp, 96 * I_ / 4);
    to_half_kernel<<<128, 256>>>(dt_proj_w, w_dt, I_ * R_ / 4);
    to_half_kernel<<<2048, 256>>>(out_proj_w, w_out, H_ * I_ / 4);
    to_half_kernel<<<2816, 256>>>(gate_w, w_gate, M_MLP * H_ / 4);
    to_half_kernel<<<2816, 256>>>(up_w, w_up, M_MLP * H_ / 4);
    to_half_kernel<<<2816, 256>>>(down_w, w_down, H_ * M_MLP / 4);

    rmsnorm_kernel<<<BT_, 256>>>(x, mixer_norm_w, h);
    // proj_h = h @ in_proj^T   (16384 x 4096 x 1024), half out
    hgemm<<<dim3(32, 128), 256, GEMM_SMEM>>>(h, H_, w_in, nullptr, nullptr,
                                             nullptr, proj_h, 4096, H_, 0, 4096);
    conv_silu_kernel<<<BT_ * 512 / 256, 256>>>(proj_h, conv_w, conv_b, xi);
    // sp = xi @ x_proj^T     (16384 x 96 x 2048), fp32 + half out
    hgemm<<<dim3(1, 128), 256, GEMM_SMEM>>>(xi, I_, w_xp, nullptr, nullptr, sp,
                                            sp_h, 96, I_, 0, 96);
    // dt = softplus(sp[:,:64] @ dt_proj^T + b)   (16384 x 2048 x 64)
    hgemm<<<dim3(16, 128), 256, GEMM_SMEM>>>(sp_h, 96, w_dt, dt_proj_b, nullptr,
                                             dt, nullptr, I_, R_, 1, I_);
    // scan + fused (y + xi*D)*silu(gate) -> y_h
    scan_kernel<<<(B_ * I_) / 16, 256>>>(dt, sp, xi, A_log, proj_h, Dv, y_h);
    // x2 = x + y @ out_proj^T   (16384 x 1024 x 2048)
    hgemm<<<dim3(8, 128), 256, GEMM_SMEM>>>(y_h, I_, w_out, x, nullptr, x2,
                                            nullptr, H_, I_, 2, H_);
    rmsnorm_kernel<<<BT_, 256>>>(x2, mlp_norm_w, h);
    // gate(half) = h @ gate_w^T   (16384 x 2816 x 1024)
    hgemm<<<dim3(22, 128), 256, GEMM_SMEM>>>(h, H_, w_gate, nullptr, nullptr,
                                             nullptr, proj_h, M_MLP, H_, 0,
                                             M_MLP);
    // act = half(silu(gate) * (h @ up_w^T))
    hgemm<<<dim3(22, 128), 256, GEMM_SMEM>>>(h, H_, w_up, nullptr, proj_h,
                                             nullptr, act, M_MLP, H_, 3, M_MLP);
    // out = x2 + act @ down_w^T   (16384 x 1024 x 2816)
    hgemm<<<dim3(8, 128), 256, GEMM_SMEM>>>(act, M_MLP, w_down, x2, nullptr,
                                            out, nullptr, H_, M_MLP, 2, H_);
}

// round 9
// speedup vs baseline: 1.3978x; 1.3978x over previous
#include <cuda_runtime.h>
#include <cuda_fp16.h>
#include <cstdint>

#define BT_ 16384
#define T_ 2048
#define B_ 8
#define H_ 1024
#define I_ 2048
#define N_SSM 16
#define R_ 64
#define M_MLP 2816

// ------------------------- scratch (device globals) --------------------------
__device__ __half g_h[BT_ * H_];        // rmsnorm out (half, GEMM A)
__device__ __half g_proj_h[BT_ * 4096]; // in_proj out / MLP gate out (half)
__device__ __half g_xi[BT_ * I_];       // conv+silu out (half)
__device__ float  g_sp[BT_ * 96];       // x_proj out fp32 (scan B/C)
__device__ __half g_sp_h[BT_ * 96];     // x_proj out half (dt GEMM A)
__device__ float  g_dt[BT_ * I_];       // softplus dt (fp32, scan)
__device__ float  g_y[BT_ * I_];        // scan out fp32
__device__ __half g_y_h[BT_ * I_];      // gated y half (out_proj A)
__device__ float  g_x2[BT_ * H_];       // mixer residual out
__device__ __half g_act[BT_ * M_MLP];   // silu(gate)*up (half, down A)
__device__ __half g_w_in[4096 * H_];
__device__ __half g_w_xp[96 * I_];
__device__ __half g_w_dt[I_ * R_];
__device__ __half g_w_out[H_ * I_];
__device__ __half g_w_gate[M_MLP * H_];
__device__ __half g_w_up[M_MLP * H_];
__device__ __half g_w_down[H_ * M_MLP];

__device__ __forceinline__ float siluf(float g) {
    return g * (1.0f / (1.0f + __expf(-g)));
}
__device__ __forceinline__ uint32_t smem_u32(const void* p) {
    return (uint32_t)__cvta_generic_to_shared(p);
}
__device__ __forceinline__ void cp4(uint32_t dst, const void* src) {
    asm volatile("cp.async.ca.shared.global [%0], [%1], 4;" ::"r"(dst), "l"(src));
}
#define CP_COMMIT() asm volatile("cp.async.commit_group;" ::: "memory")
#define CP_WAIT2() asm volatile("cp.async.wait_group 2;" ::: "memory")

// mma.sync m16n8k16 f16 -> f32 accum
#define MMA16(d, a0, a1, a2, a3, b0, b1)                                       \
    asm volatile(                                                              \
        "mma.sync.aligned.m16n8k16.row.col.f32.f16.f16.f32 "                   \
        "{%0,%1,%2,%3},{%4,%5,%6,%7},{%8,%9},{%0,%1,%2,%3};"                   \
        : "+f"((d)[0]), "+f"((d)[1]), "+f"((d)[2]), "+f"((d)[3])               \
        : "r"(a0), "r"(a1), "r"(a2), "r"(a3), "r"(b0), "r"(b1))

// ------------------------- fp16 mma.sync GEMM (R5 config) --------------------
// C[M,N] = A[M,K] @ W[N,K]^T, A/W half K-major. BM=BN=128, BK=32, 4 stages,
// 8 warps (2m x 4n), warp tile 64x32, 2 CTAs/SM.
// Smem row = 32 halfs (64B), k-pair-permuted: pair kp at pair-pos
// pp = 4*(kp&3) + ((kp>>2)&1) + 2*(kp>>3); one LDS.128 at (row, qc*16B) =
// the m16n8k16 fragment k-slices for both k-steps.
// mode 0: C fp32 (if C) and/or Ch half (if Ch); 1: softplus(acc+aux[n])->C;
// 2: acc+aux[m*N+n]->C; 3: half(acc*silu(auxh[m*N+n]))->Ch
#define STAGES 4
#define STG_U32 4096  // A 2048 + B 2048 (u32 units)
#define GEMM_SMEM (STAGES * STG_U32 * 4)  // 64 KB

__global__ __launch_bounds__(256, 2) void hgemm(
    const __half* __restrict__ A, int lda, const __half* __restrict__ W,
    const float* __restrict__ aux, const __half* __restrict__ auxh,
    float* __restrict__ C, __half* __restrict__ Ch, int N, int K, int mode,
    int n_valid) {
    extern __shared__ uint32_t sm[];
    const int tid = threadIdx.x;
    const int lane = tid & 31, wid = tid >> 5;
    const int wm = wid & 1, wn = wid >> 1;
    const int qr = lane >> 2, qc = lane & 3;
    const int bm = blockIdx.y * 128, bn = blockIdx.x * 128;
    const int nk = K >> 5;

    float acc[4][4][4];
#pragma unroll
    for (int mi = 0; mi < 4; mi++)
#pragma unroll
        for (int ni = 0; ni < 4; ni++)
#pragma unroll
            for (int q = 0; q < 4; q++) acc[mi][ni][q] = 0.f;

    auto load_stage = [&](int s, int kt) {
        uint32_t* sA = sm + s * STG_U32;
        uint32_t* sB = sA + 2048;
#pragma unroll
        for (int i = 0; i < 8; i++) {
            int w = tid + i * 256;
            int row = w >> 4, kp = w & 15;
            int pp = 4 * (kp & 3) + ((kp >> 2) & 1) + 2 * (kp >> 3);
            cp4(smem_u32(sA + row * 16 + pp),
                A + (size_t)(bm + row) * lda + kt * 32 + 2 * kp);
        }
#pragma unroll
        for (int i = 0; i < 8; i++) {
            int w = tid + i * 256;
            int row = w >> 4, kp = w & 15;
            int pp = 4 * (kp & 3) + ((kp >> 2) & 1) + 2 * (kp >> 3);
            if (bn + row < n_valid)
                cp4(smem_u32(sB + row * 16 + pp),
                    W + (size_t)(bn + row) * (size_t)K + kt * 32 + 2 * kp);
        }
    };

    for (int s = 0; s < STAGES - 1; s++) {
        if (s < nk) load_stage(s, s);
        CP_COMMIT();
    }

    for (int kt = 0; kt < nk; kt++) {
        CP_WAIT2();
        __syncthreads();
        int pf = kt + STAGES - 1;
        if (pf < nk) load_stage(pf & 3, pf);
        CP_COMMIT();

        const uint32_t* As = sm + (kt & 3) * STG_U32;
        const uint32_t* Bs = As + 2048;
        uint4 alo[4], ahi[4], bb[4];
#pragma unroll
        for (int mi = 0; mi < 4; mi++) {
            int r = wm * 64 + mi * 16 + qr;
            alo[mi] = *(const uint4*)(As + r * 16 + qc * 4);
            ahi[mi] = *(const uint4*)(As + (r + 8) * 16 + qc * 4);
        }
#pragma unroll
        for (int ni = 0; ni < 4; ni++) {
            int r = wn * 32 + ni * 8 + qr;
            bb[ni] = *(const uint4*)(Bs + r * 16 + qc * 4);
        }
#pragma unroll
        for (int mi = 0; mi < 4; mi++)
#pragma unroll
            for (int ni = 0; ni < 4; ni++) {
                MMA16(acc[mi][ni], alo[mi].x, ahi[mi].x, alo[mi].y, ahi[mi].y,
                      bb[ni].x, bb[ni].y);
                MMA16(acc[mi][ni], alo[mi].z, ahi[mi].z, alo[mi].w, ahi[mi].w,
                      bb[ni].z, bb[ni].w);
            }
    }

    // epilogue: thread holds (r0,c0),(r0,c0+1),(r0+8,c0),(r0+8,c0+1) per tile
#pragma unroll
    for (int mi = 0; mi < 4; mi++) {
#pragma unroll
        for (int ni = 0; ni < 4; ni++) {
            int r0 = bm + wm * 64 + mi * 16 + qr;
            int c0 = bn + wn * 32 + ni * 8 + 2 * qc;
            if (c0 >= n_valid) continue;
            float v00 = acc[mi][ni][0], v01 = acc[mi][ni][1];
            float v10 = acc[mi][ni][2], v11 = acc[mi][ni][3];
            size_t g0 = (size_t)r0 * (size_t)N + c0;
            size_t g1 = g0 + (size_t)8 * N;
            if (mode == 1) {
                float b0 = __ldg(aux + c0), b1 = __ldg(aux + c0 + 1);
                float z;
                z = v00 + b0; v00 = fmaxf(z, 0.f) + log1pf(__expf(-fabsf(z)));
                z = v01 + b1; v01 = fmaxf(z, 0.f) + log1pf(__expf(-fabsf(z)));
                z = v10 + b0; v10 = fmaxf(z, 0.f) + log1pf(__expf(-fabsf(z)));
                z = v11 + b1; v11 = fmaxf(z, 0.f) + log1pf(__expf(-fabsf(z)));
                *(float2*)(C + g0) = make_float2(v00, v01);
                *(float2*)(C + g1) = make_float2(v10, v11);
            } else if (mode == 2) {
                float2 r0v = *(const float2*)(aux + g0);
                float2 r1v = *(const float2*)(aux + g1);
                *(float2*)(C + g0) = make_float2(v00 + r0v.x, v01 + r0v.y);
                *(float2*)(C + g1) = make_float2(v10 + r1v.x, v11 + r1v.y);
            } else if (mode == 3) {
                __half2 a0v = *(const __half2*)(auxh + g0);
                __half2 a1v = *(const __half2*)(auxh + g1);
                *(__half2*)(Ch + g0) = __floats2half2_rn(
                    v00 * siluf(__low2float(a0v)), v01 * siluf(__high2float(a0v)));
                *(__half2*)(Ch + g1) = __floats2half2_rn(
                    v10 * siluf(__low2float(a1v)), v11 * siluf(__high2float(a1v)));
            } else {
                if (C != nullptr) {
                    *(float2*)(C + g0) = make_float2(v00, v01);
                    *(float2*)(C + g1) = make_float2(v10, v11);
                }
                if (Ch != nullptr) {
                    *(__half2*)(Ch + g0) = __floats2half2_rn(v00, v01);
                    *(__half2*)(Ch + g1) = __floats2half2_rn(v10, v11);
                }
            }
        }
    }
}

// --------------------------- fp32 -> fp16 convert ----------------------------
__global__ void to_half_kernel(const float* __restrict__ src,
                               __half* __restrict__ dst, int n4) {
    int i = blockIdx.x * 256 + threadIdx.x;
    if (i < n4) {
        float4 v = ((const float4*)src)[i];
        __half2 h0 = __floats2half2_rn(v.x, v.y);
        __half2 h1 = __floats2half2_rn(v.z, v.w);
        uint2 o;
        o.x = *(uint32_t*)&h0;
        o.y = *(uint32_t*)&h1;
        ((uint2*)dst)[i] = o;
    }
}

// ------------------------------- rmsnorm (-> half) ---------------------------
__global__ void rmsnorm_kernel(const float* __restrict__ x,
                               const float* __restrict__ w,
                               __half* __restrict__ out) {
    int row = blockIdx.x;
    int t = threadIdx.x;
    const float4* xr = (const float4*)(x + (size_t)row * H_);
    float4 v = xr[t];
    float ss = v.x * v.x + v.y * v.y + v.z * v.z + v.w * v.w;
#pragma unroll
    for (int o = 16; o > 0; o >>= 1) ss += __shfl_down_sync(0xffffffffu, ss, o);
    __shared__ float red[8];
    if ((t & 31) == 0) red[t >> 5] = ss;
    __syncthreads();
    float tot = red[0] + red[1] + red[2] + red[3] + red[4] + red[5] + red[6] + red[7];
    float scale = rsqrtf(tot * (1.0f / (float)H_) + 1e-5f);
    float4 wv = ((const float4*)w)[t];
    __half2 h0 = __floats2half2_rn(v.x * scale * wv.x, v.y * scale * wv.y);
    __half2 h1 = __floats2half2_rn(v.z * scale * wv.z, v.w * scale * wv.w);
    uint2 o;
    o.x = *(uint32_t*)&h0;
    o.y = *(uint32_t*)&h1;
    ((uint2*)(out + (size_t)row * H_))[t] = o;
}

// ---------------- causal depthwise conv + silu (half in, half out) -----------
__global__ void conv_silu_kernel(const __half* __restrict__ proj,
                                 const float* __restrict__ cw,
                                 const float* __restrict__ cb,
                                 __half* __restrict__ xi) {
    int idx = blockIdx.x * blockDim.x + threadIdx.x;
    int i4 = idx & 511;
    int bt = idx >> 9;
    int t = bt & (T_ - 1);
    const float4* cwv = (const float4*)cw;
    float w[4][4];
#pragma unroll
    for (int c = 0; c < 4; c++) {
        float4 tmp = cwv[i4 * 4 + c];
        w[c][0] = tmp.x; w[c][1] = tmp.y; w[c][2] = tmp.z; w[c][3] = tmp.w;
    }
    float4 cbv = ((const float4*)cb)[i4];
    float acc[4] = {cbv.x, cbv.y, cbv.z, cbv.w};
    const __half* base = proj + (size_t)bt * 4096 + i4 * 4;
#pragma unroll
    for (int k = 0; k < 4; ++k) {
        int back = 3 - k;
        if (t >= back) {
            uint2 pr = *(const uint2*)(base - (size_t)back * 4096);
            __half2 p0 = *(__half2*)&pr.x;
            __half2 p1 = *(__half2*)&pr.y;
            acc[0] += __low2float(p0) * w[0][k];
            acc[1] += __high2float(p0) * w[1][k];
            acc[2] += __low2float(p1) * w[2][k];
            acc[3] += __high2float(p1) * w[3][k];
        }
    }
    __half2 h0 = __floats2half2_rn(siluf(acc[0]), siluf(acc[1]));
    __half2 h1 = __floats2half2_rn(siluf(acc[2]), siluf(acc[3]));
    uint2 o;
    o.x = *(uint32_t*)&h0;
    o.y = *(uint32_t*)&h1;
    ((uint2*)xi)[idx] = o;
}

// ------------------------------ selective scan (R5 form) ---------------------
__global__ __launch_bounds__(256) void scan_kernel(
    const float* __restrict__ dt, const float* __restrict__ sp,
    const __half* __restrict__ xi, const float* __restrict__ A_log,
    float* __restrict__ y) {
    __shared__ float sBC[64][32];
    int tid = threadIdx.x;
    int warp = tid >> 5, lane = tid & 31;
    int half_ = lane >> 4, n = lane & 15;
    int chan = blockIdx.x * 16 + warp * 2 + half_;
    int b = chan >> 11;
    int i = chan & (I_ - 1);
    float A = -__expf(__ldg(A_log + i * N_SSM + n));
    size_t rowoff = (size_t)b * T_ * I_ + i;
    size_t spoff = (size_t)b * T_ * 96;
    float s = 0.f;

    for (int t0 = 0; t0 < T_; t0 += 64) {
        __syncthreads();
#pragma unroll
        for (int q = tid; q < 512; q += 256) {
            int r = q >> 3, c = (q & 7) << 2;
            *(float4*)&sBC[r][c] =
                *(const float4*)(sp + spoff + (size_t)(t0 + r) * 96 + 64 + c);
        }
        __syncthreads();
        size_t off = rowoff + (size_t)t0 * I_;
        for (int tl = 0; tl < 64; ++tl, off += I_) {
            float dtv = __ldg(dt + off);
            float xv = __half2float(__ldg(xi + off));
            float dA = __expf(dtv * A);
            s = fmaf(dA, s, dtv * xv * sBC[tl][n]);
            float yv = s * sBC[tl][16 + n];
            yv += __shfl_down_sync(0xffffffffu, yv, 8, 16);
            yv += __shfl_down_sync(0xffffffffu, yv, 4, 16);
            yv += __shfl_down_sync(0xffffffffu, yv, 2, 16);
            yv += __shfl_down_sync(0xffffffffu, yv, 1, 16);
            if (n == 0) y[off] = yv;
        }
    }
}

// --------------- y_h = half((y + xi*D) * silu(gate_half)) --------------------
__global__ void ypost_kernel(const float* __restrict__ y,
                             const __half* __restrict__ xi,
                             const float* __restrict__ D,
                             const __half* __restrict__ proj,
                             __half* __restrict__ yh) {
    size_t idx = (size_t)blockIdx.x * 256 + threadIdx.x;
    size_t i4 = idx & 511;
    size_t bt = idx >> 9;
    float4 yv = ((const float4*)y)[idx];
    uint2 xr = ((const uint2*)xi)[idx];
    __half2 x0 = *(__half2*)&xr.x;
    __half2 x1 = *(__half2*)&xr.y;
    float4 dv = ((const float4*)D)[i4];
    uint2 gr = *(const uint2*)(proj + bt * 4096 + I_ + i4 * 4);
    __half2 g0 = *(__half2*)&gr.x;
    __half2 g1 = *(__half2*)&gr.y;
    float o0 = (yv.x + __low2float(x0) * dv.x) * siluf(__low2float(g0));
    float o1 = (yv.y + __high2float(x0) * dv.y) * siluf(__high2float(g0));
    float o2 = (yv.z + __low2float(x1) * dv.z) * siluf(__low2float(g1));
    float o3 = (yv.w + __high2float(x1) * dv.w) * siluf(__high2float(g1));
    __half2 h0 = __floats2half2_rn(o0, o1);
    __half2 h1 = __floats2half2_rn(o2, o3);
    uint2 o;
    o.x = *(uint32_t*)&h0;
    o.y = *(uint32_t*)&h1;
    ((uint2*)yh)[idx] = o;
}

// ------------------------------- launch --------------------------------------
extern "C" void kernel_launch(void* const* d_in, const int* in_sizes, int n_in,
                              void* d_out, int out_size) {
    const float* x            = (const float*)d_in[0];
    const float* mixer_norm_w = (const float*)d_in[1];
    const float* in_proj_w    = (const float*)d_in[2];
    const float* conv_w       = (const float*)d_in[3];
    const float* conv_b       = (const float*)d_in[4];
    const float* x_proj_w     = (const float*)d_in[5];
    const float* dt_proj_w    = (const float*)d_in[6];
    const float* dt_proj_b    = (const float*)d_in[7];
    const float* A_log        = (const float*)d_in[8];
    const float* Dv           = (const float*)d_in[9];
    const float* out_proj_w   = (const float*)d_in[10];
    const float* mlp_norm_w   = (const float*)d_in[11];
    const float* gate_w       = (const float*)d_in[12];
    const float* up_w         = (const float*)d_in[13];
    const float* down_w       = (const float*)d_in[14];
    float* out = (float*)d_out;

    __half *h, *proj_h, *xi, *sp_h, *y_h, *act;
    float *sp, *dt, *y, *x2;
    __half *w_in, *w_xp, *w_dt, *w_out, *w_gate, *w_up, *w_down;
    cudaGetSymbolAddress((void**)&h, g_h);
    cudaGetSymbolAddress((void**)&proj_h, g_proj_h);
    cudaGetSymbolAddress((void**)&xi, g_xi);
    cudaGetSymbolAddress((void**)&sp, g_sp);
    cudaGetSymbolAddress((void**)&sp_h, g_sp_h);
    cudaGetSymbolAddress((void**)&dt, g_dt);
    cudaGetSymbolAddress((void**)&y, g_y);
    cudaGetSymbolAddress((void**)&y_h, g_y_h);
    cudaGetSymbolAddress((void**)&x2, g_x2);
    cudaGetSymbolAddress((void**)&act, g_act);
    cudaGetSymbolAddress((void**)&w_in, g_w_in);
    cudaGetSymbolAddress((void**)&w_xp, g_w_xp);
    cudaGetSymbolAddress((void**)&w_dt, g_w_dt);
    cudaGetSymbolAddress((void**)&w_out, g_w_out);
    cudaGetSymbolAddress((void**)&w_gate, g_w_gate);
    cudaGetSymbolAddress((void**)&w_up, g_w_up);
    cudaGetSymbolAddress((void**)&w_down, g_w_down);

    cudaFuncSetAttribute(hgemm, cudaFuncAttributeMaxDynamicSharedMemorySize,
                         GEMM_SMEM);

    to_half_kernel<<<4096, 256>>>(in_proj_w, w_in, 4096 * H_ / 4);
    to_half_kernel<<<192, 256>>>(x_proj_w, w_xp, 96 * I_ / 4);
    to_half_kernel<<<128, 256>>>(dt_proj_w, w_dt, I_ * R_ / 4);
    to_half_kernel<<<2048, 256>>>(out_proj_w, w_out, H_ * I_ / 4);
    to_half_kernel<<<2816, 256>>>(gate_w, w_gate, M_MLP * H_ / 4);
    to_half_kernel<<<2816, 256>>>(up_w, w_up, M_MLP * H_ / 4);
    to_half_kernel<<<2816, 256>>>(down_w, w_down, H_ * M_MLP / 4);

    rmsnorm_kernel<<<BT_, 256>>>(x, mixer_norm_w, h);
    // proj_h = h @ in_proj^T   (16384 x 4096 x 1024), half out
    hgemm<<<dim3(32, 128), 256, GEMM_SMEM>>>(h, H_, w_in, nullptr, nullptr,
                                             nullptr, proj_h, 4096, H_, 0, 4096);
    conv_silu_kernel<<<BT_ * 512 / 256, 256>>>(proj_h, conv_w, conv_b, xi);
    // sp = xi @ x_proj^T     (16384 x 96 x 2048), fp32 + half out
    hgemm<<<dim3(1, 128), 256, GEMM_SMEM>>>(xi, I_, w_xp, nullptr, nullptr, sp,
                                            sp_h, 96, I_, 0, 96);
    // dt = softplus(sp[:,:64] @ dt_proj^T + b)   (16384 x 2048 x 64)
    hgemm<<<dim3(16, 128), 256, GEMM_SMEM>>>(sp_h, 96, w_dt, dt_proj_b, nullptr,
                                             dt, nullptr, I_, R_, 1, I_);
    // scan -> y (fp32)
    scan_kernel<<<(B_ * I_) / 16, 256>>>(dt, sp, xi, A_log, y);
    // y_h = half((y + xi*D) * silu(gate))
    ypost_kernel<<<BT_ * 512 / 256, 256>>>(y, xi, Dv, proj_h, y_h);
    // x2 = x + y @ out_proj^T   (16384 x 1024 x 2048)
    hgemm<<<dim3(8, 128), 256, GEMM_SMEM>>>(y_h, I_, w_out, x, nullptr, x2,
                                            nullptr, H_, I_, 2, H_);
    rmsnorm_kernel<<<BT_, 256>>>(x2, mlp_norm_w, h);
    // gate(half) = h @ gate_w^T   (16384 x 2816 x 1024)
    hgemm<<<dim3(22, 128), 256, GEMM_SMEM>>>(h, H_, w_gate, nullptr, nullptr,
                                             nullptr, proj_h, M_MLP, H_, 0,
                                             M_MLP);
    // act = half(silu(gate) * (h @ up_w^T))
    hgemm<<<dim3(22, 128), 256, GEMM_SMEM>>>(h, H_, w_up, nullptr, proj_h,
                                             nullptr, act, M_MLP, H_, 3, M_MLP);
    // out = x2 + act @ down_w^T   (16384 x 1024 x 2816)
    hgemm<<<dim3(8, 128), 256, GEMM_SMEM>>>(act, M_MLP, w_down, x2, nullptr,
                                            out, nullptr, H_, M_MLP, 2, H_);
}

// round 12
// speedup vs baseline: 1.5091x; 1.0796x over previous
#include <cuda_runtime.h>
#include <cuda_fp16.h>
#include <cstdint>

#define BT_ 16384
#define T_ 2048
#define B_ 8
#define H_ 1024
#define I_ 2048
#define N_SSM 16
#define R_ 64
#define M_MLP 2816

// ------------------------- scratch (device globals) --------------------------
__device__ __half g_h[BT_ * H_];        // rmsnorm out (half, GEMM A)
__device__ __half g_proj_h[BT_ * 4096]; // in_proj out / MLP gate out (half)
__device__ __half g_xi[BT_ * I_];       // conv+silu out (half)
__device__ float  g_sp[BT_ * 96];       // x_proj out fp32 (scan B/C)
__device__ __half g_sp_h[BT_ * 96];     // x_proj out half (dt GEMM A)
__device__ float  g_dt[BT_ * I_];       // softplus dt (fp32, scan)
__device__ float  g_y[BT_ * I_];        // scan out fp32
__device__ __half g_y_h[BT_ * I_];      // gated y half (out_proj A)
__device__ float  g_x2[BT_ * H_];       // mixer residual out
__device__ __half g_act[BT_ * M_MLP];   // silu(gate)*up (half, down A)
// weights: fp16, k-permuted within 32-element blocks (GEMM-only consumers)
__device__ __half g_w_in[4096 * H_];
__device__ __half g_w_xp[96 * I_];
__device__ __half g_w_dt[I_ * R_];
__device__ __half g_w_out[H_ * I_];
__device__ __half g_w_gate[M_MLP * H_];
__device__ __half g_w_up[M_MLP * H_];
__device__ __half g_w_down[H_ * M_MLP];

__device__ __forceinline__ float siluf(float g) {
    return g * (1.0f / (1.0f + __expf(-g)));
}
// k-pair permutation within 32-half blocks:
// pair kp (0..15) -> pos pp = 4*(kp&3) + ((kp>>2)&1) + 2*(kp>>3)
__device__ __forceinline__ int ppf(int kp) {
    return 4 * (kp & 3) + ((kp >> 2) & 1) + 2 * (kp >> 3);
}
__device__ __forceinline__ int permk(int k) {  // true k -> stored pos (0..31)
    return 2 * ppf(k >> 1) + (k & 1);
}
__device__ __forceinline__ uint32_t smem_u32(const void* p) {
    return (uint32_t)__cvta_generic_to_shared(p);
}
__device__ __forceinline__ void cp4(uint32_t dst, const void* src) {
    asm volatile("cp.async.ca.shared.global [%0], [%1], 4;" ::"r"(dst), "l"(src));
}
__device__ __forceinline__ void cp16(uint32_t dst, const void* src) {
    asm volatile("cp.async.cg.shared.global [%0], [%1], 16;" ::"r"(dst), "l"(src));
}
#define CP_COMMIT() asm volatile("cp.async.commit_group;" ::: "memory")
#define CP_WAIT2() asm volatile("cp.async.wait_group 2;" ::: "memory")

// mma.sync m16n8k16 f16 -> f32 accum
#define MMA16(d, a0, a1, a2, a3, b0, b1)                                       \
    asm volatile(                                                              \
        "mma.sync.aligned.m16n8k16.row.col.f32.f16.f16.f32 "                   \
        "{%0,%1,%2,%3},{%4,%5,%6,%7},{%8,%9},{%0,%1,%2,%3};"                   \
        : "+f"((d)[0]), "+f"((d)[1]), "+f"((d)[2]), "+f"((d)[3])               \
        : "r"(a0), "r"(a1), "r"(a2), "r"(a3), "r"(b0), "r"(b1))

// ------------------------- fp16 mma.sync GEMM --------------------------------
// C[M,N] = A[M,K] @ W[N,K]^T. A half K-major true order (permuted on the fly,
// 4B cp.async); W half K-major PRE-PERMUTED in gmem (16B cp.async).
// BM=BN=128, BK=32, 4 stages, 8 warps (2m x 4n), warp tile 64x32, 2 CTAs/SM.
// Smem row = 32 halfs; one LDS.128 at (row, qc*16B) = m16n8k16 fragment
// k-slices for both k-steps.
// mode 0: C fp32 (if C) and/or Ch half (if Ch); 1: softplus(acc+aux[n])->C;
// 2: acc+aux[m*N+n]->C; 3: half(acc*silu(auxh[m*N+n]))->Ch
#define STAGES 4
#define STG_U32 4096  // A 2048 + B 2048 (u32 units)
#define GEMM_SMEM (STAGES * STG_U32 * 4)  // 64 KB

__global__ __launch_bounds__(256, 2) void hgemm(
    const __half* __restrict__ A, int lda, const __half* __restrict__ W,
    const float* __restrict__ aux, const __half* __restrict__ auxh,
    float* __restrict__ C, __half* __restrict__ Ch, int N, int K, int mode,
    int n_valid) {
    extern __shared__ uint32_t sm[];
    const int tid = threadIdx.x;
    const int lane = tid & 31, wid = tid >> 5;
    const int wm = wid & 1, wn = wid >> 1;
    const int qr = lane >> 2, qc = lane & 3;
    const int bm = blockIdx.y * 128, bn = blockIdx.x * 128;
    const int nk = K >> 5;

    float acc[4][4][4];
#pragma unroll
    for (int mi = 0; mi < 4; mi++)
#pragma unroll
        for (int ni = 0; ni < 4; ni++)
#pragma unroll
            for (int q = 0; q < 4; q++) acc[mi][ni][q] = 0.f;

    auto load_stage = [&](int s, int kt) {
        uint32_t* sA = sm + s * STG_U32;
        uint32_t* sB = sA + 2048;
        // A: 4B copies with on-the-fly k-pair permutation (R9-proven path)
#pragma unroll
        for (int i = 0; i < 8; i++) {
            int w = tid + i * 256;
            int row = w >> 4, kp = w & 15;
            int pp = 4 * (kp & 3) + ((kp >> 2) & 1) + 2 * (kp >> 3);
            cp4(smem_u32(sA + row * 16 + pp),
                A + (size_t)(bm + row) * lda + kt * 32 + 2 * kp);
        }
        // B: contiguous 16B copies from pre-permuted weights
#pragma unroll
        for (int i = 0; i < 2; i++) {
            int ch = tid + i * 256;       // 512 16B chunks
            int r = ch >> 2, c = ch & 3;  // row, chunk within row
            if (bn + r < n_valid)
                cp16(smem_u32(sB + r * 16 + c * 4),
                     W + (size_t)(bn + r) * (size_t)K + kt * 32 + c * 8);
        }
    };

    for (int s = 0; s < STAGES - 1; s++) {
        if (s < nk) load_stage(s, s);
        CP_COMMIT();
    }

    for (int kt = 0; kt < nk; kt++) {
        CP_WAIT2();
        __syncthreads();
        int pf = kt + STAGES - 1;
        if (pf < nk) load_stage(pf & 3, pf);
        CP_COMMIT();

        const uint32_t* As = sm + (kt & 3) * STG_U32;
        const uint32_t* Bs = As + 2048;
        uint4 alo[4], ahi[4], bb[4];
#pragma unroll
        for (int mi = 0; mi < 4; mi++) {
            int r = wm * 64 + mi * 16 + qr;
            alo[mi] = *(const uint4*)(As + r * 16 + qc * 4);
            ahi[mi] = *(const uint4*)(As + (r + 8) * 16 + qc * 4);
        }
#pragma unroll
        for (int ni = 0; ni < 4; ni++) {
            int r = wn * 32 + ni * 8 + qr;
            bb[ni] = *(const uint4*)(Bs + r * 16 + qc * 4);
        }
#pragma unroll
        for (int mi = 0; mi < 4; mi++)
#pragma unroll
            for (int ni = 0; ni < 4; ni++) {
                MMA16(acc[mi][ni], alo[mi].x, ahi[mi].x, alo[mi].y, ahi[mi].y,
                      bb[ni].x, bb[ni].y);
                MMA16(acc[mi][ni], alo[mi].z, ahi[mi].z, alo[mi].w, ahi[mi].w,
                      bb[ni].z, bb[ni].w);
            }
    }

    // epilogue: thread holds (r0,c0),(r0,c0+1),(r0+8,c0),(r0+8,c0+1) per tile
#pragma unroll
    for (int mi = 0; mi < 4; mi++) {
#pragma unroll
        for (int ni = 0; ni < 4; ni++) {
            int r0 = bm + wm * 64 + mi * 16 + qr;
            int c0 = bn + wn * 32 + ni * 8 + 2 * qc;
            if (c0 >= n_valid) continue;
            float v00 = acc[mi][ni][0], v01 = acc[mi][ni][1];
            float v10 = acc[mi][ni][2], v11 = acc[mi][ni][3];
            size_t g0 = (size_t)r0 * (size_t)N + c0;
            size_t g1 = g0 + (size_t)8 * N;
            if (mode == 1) {
                float b0 = __ldg(aux + c0), b1 = __ldg(aux + c0 + 1);
                float z;
                z = v00 + b0; v00 = fmaxf(z, 0.f) + log1pf(__expf(-fabsf(z)));
                z = v01 + b1; v01 = fmaxf(z, 0.f) + log1pf(__expf(-fabsf(z)));
                z = v10 + b0; v10 = fmaxf(z, 0.f) + log1pf(__expf(-fabsf(z)));
                z = v11 + b1; v11 = fmaxf(z, 0.f) + log1pf(__expf(-fabsf(z)));
                *(float2*)(C + g0) = make_float2(v00, v01);
                *(float2*)(C + g1) = make_float2(v10, v11);
            } else if (mode == 2) {
                float2 r0v = *(const float2*)(aux + g0);
                float2 r1v = *(const float2*)(aux + g1);
                *(float2*)(C + g0) = make_float2(v00 + r0v.x, v01 + r0v.y);
                *(float2*)(C + g1) = make_float2(v10 + r1v.x, v11 + r1v.y);
            } else if (mode == 3) {
                __half2 a0v = *(const __half2*)(auxh + g0);
                __half2 a1v = *(const __half2*)(auxh + g1);
                *(__half2*)(Ch + g0) = __floats2half2_rn(
                    v00 * siluf(__low2float(a0v)), v01 * siluf(__high2float(a0v)));
                *(__half2*)(Ch + g1) = __floats2half2_rn(
                    v10 * siluf(__low2float(a1v)), v11 * siluf(__high2float(a1v)));
            } else {
                if (C != nullptr) {
                    *(float2*)(C + g0) = make_float2(v00, v01);
                    *(float2*)(C + g1) = make_float2(v10, v11);
                }
                if (Ch != nullptr) {
                    *(__half2*)(Ch + g0) = __floats2half2_rn(v00, v01);
                    *(__half2*)(Ch + g1) = __floats2half2_rn(v10, v11);
                }
            }
        }
    }
}

// ------------- fp32 -> fp16 weight convert + k-block permute -----------------
// dst[base + permk(kl)] = half(src[base + kl]); row K % 32 == 0 so blocks
// never cross rows.
__global__ void to_half_perm_kernel(const float* __restrict__ src,
                                    __half* __restrict__ dst, int n_total) {
    int i = blockIdx.x * 256 + threadIdx.x;
    if (i < n_total) {
        int base = i & ~31;
        int kl = i & 31;
        dst[base + permk(kl)] = __float2half_rn(src[i]);
    }
}

// ------------------------------- rmsnorm (-> half) ---------------------------
__global__ void rmsnorm_kernel(const float* __restrict__ x,
                               const float* __restrict__ w,
                               __half* __restrict__ out) {
    int row = blockIdx.x;
    int t = threadIdx.x;
    const float4* xr = (const float4*)(x + (size_t)row * H_);
    float4 v = xr[t];
    float ss = v.x * v.x + v.y * v.y + v.z * v.z + v.w * v.w;
#pragma unroll
    for (int o = 16; o > 0; o >>= 1) ss += __shfl_down_sync(0xffffffffu, ss, o);
    __shared__ float red[8];
    if ((t & 31) == 0) red[t >> 5] = ss;
    __syncthreads();
    float tot = red[0] + red[1] + red[2] + red[3] + red[4] + red[5] + red[6] + red[7];
    float scale = rsqrtf(tot * (1.0f / (float)H_) + 1e-5f);
    float4 wv = ((const float4*)w)[t];
    __half2 h0 = __floats2half2_rn(v.x * scale * wv.x, v.y * scale * wv.y);
    __half2 h1 = __floats2half2_rn(v.z * scale * wv.z, v.w * scale * wv.w);
    uint2 o;
    o.x = *(uint32_t*)&h0;
    o.y = *(uint32_t*)&h1;
    ((uint2*)(out + (size_t)row * H_))[t] = o;
}

// ---------------- causal depthwise conv + silu (half in, half out) -----------
__global__ void conv_silu_kernel(const __half* __restrict__ proj,
                                 const float* __restrict__ cw,
                                 const float* __restrict__ cb,
                                 __half* __restrict__ xi) {
    int idx = blockIdx.x * blockDim.x + threadIdx.x;
    int i4 = idx & 511;
    int bt = idx >> 9;
    int t = bt & (T_ - 1);
    const float4* cwv = (const float4*)cw;
    float w[4][4];
#pragma unroll
    for (int c = 0; c < 4; c++) {
        float4 tmp = cwv[i4 * 4 + c];
        w[c][0] = tmp.x; w[c][1] = tmp.y; w[c][2] = tmp.z; w[c][3] = tmp.w;
    }
    float4 cbv = ((const float4*)cb)[i4];
    float acc[4] = {cbv.x, cbv.y, cbv.z, cbv.w};
    const __half* base = proj + (size_t)bt * 4096 + i4 * 4;
#pragma unroll
    for (int k = 0; k < 4; ++k) {
        int back = 3 - k;
        if (t >= back) {
            uint2 pr = *(const uint2*)(base - (size_t)back * 4096);
            __half2 p0 = *(__half2*)&pr.x;
            __half2 p1 = *(__half2*)&pr.y;
            acc[0] += __low2float(p0) * w[0][k];
            acc[1] += __high2float(p0) * w[1][k];
            acc[2] += __low2float(p1) * w[2][k];
            acc[3] += __high2float(p1) * w[3][k];
        }
    }
    __half2 h0 = __floats2half2_rn(siluf(acc[0]), siluf(acc[1]));
    __half2 h1 = __floats2half2_rn(siluf(acc[2]), siluf(acc[3]));
    uint2 o;
    o.x = *(uint32_t*)&h0;
    o.y = *(uint32_t*)&h1;
    ((uint2*)xi)[idx] = o;
}

// ------------------------------ selective scan -------------------------------
__global__ __launch_bounds__(256) void scan_kernel(
    const float* __restrict__ dt, const float* __restrict__ sp,
    const __half* __restrict__ xi, const float* __restrict__ A_log,
    float* __restrict__ y) {
    __shared__ float sBC[64][32];
    int tid = threadIdx.x;
    int warp = tid >> 5, lane = tid & 31;
    int half_ = lane >> 4, n = lane & 15;
    int chan = blockIdx.x * 16 + warp * 2 + half_;
    int b = chan >> 11;
    int i = chan & (I_ - 1);
    float A = -__expf(__ldg(A_log + i * N_SSM + n));
    size_t rowoff = (size_t)b * T_ * I_ + i;
    size_t spoff = (size_t)b * T_ * 96;
    float s = 0.f;

    for (int t0 = 0; t0 < T_; t0 += 64) {
        __syncthreads();
#pragma unroll
        for (int q = tid; q < 512; q += 256) {
            int r = q >> 3, c = (q & 7) << 2;
            *(float4*)&sBC[r][c] =
                *(const float4*)(sp + spoff + (size_t)(t0 + r) * 96 + 64 + c);
        }
        __syncthreads();
        size_t off = rowoff + (size_t)t0 * I_;
        for (int tl = 0; tl < 64; ++tl, off += I_) {
            float dtv = __ldg(dt + off);
            float xv = __half2float(__ldg(xi + off));
            float dA = __expf(dtv * A);
            s = fmaf(dA, s, dtv * xv * sBC[tl][n]);
            float yv = s * sBC[tl][16 + n];
            yv += __shfl_down_sync(0xffffffffu, yv, 8, 16);
            yv += __shfl_down_sync(0xffffffffu, yv, 4, 16);
            yv += __shfl_down_sync(0xffffffffu, yv, 2, 16);
            yv += __shfl_down_sync(0xffffffffu, yv, 1, 16);
            if (n == 0) y[off] = yv;
        }
    }
}

// --------------- y_h = half((y + xi*D) * silu(gate_half)) --------------------
__global__ void ypost_kernel(const float* __restrict__ y,
                             const __half* __restrict__ xi,
                             const float* __restrict__ D,
                             const __half* __restrict__ proj,
                             __half* __restrict__ yh) {
    size_t idx = (size_t)blockIdx.x * 256 + threadIdx.x;
    size_t i4 = idx & 511;
    size_t bt = idx >> 9;
    float4 yv = ((const float4*)y)[idx];
    uint2 xr = ((const uint2*)xi)[idx];
    __half2 x0 = *(__half2*)&xr.x;
    __half2 x1 = *(__half2*)&xr.y;
    float4 dv = ((const float4*)D)[i4];
    uint2 gr = *(const uint2*)(proj + bt * 4096 + I_ + i4 * 4);
    __half2 g0 = *(__half2*)&gr.x;
    __half2 g1 = *(__half2*)&gr.y;
    float o0 = (yv.x + __low2float(x0) * dv.x) * siluf(__low2float(g0));
    float o1 = (yv.y + __high2float(x0) * dv.y) * siluf(__high2float(g0));
    float o2 = (yv.z + __low2float(x1) * dv.z) * siluf(__low2float(g1));
    float o3 = (yv.w + __high2float(x1) * dv.w) * siluf(__high2float(g1));
    __half2 h0 = __floats2half2_rn(o0, o1);
    __half2 h1 = __floats2half2_rn(o2, o3);
    uint2 o;
    o.x = *(uint32_t*)&h0;
    o.y = *(uint32_t*)&h1;
    ((uint2*)yh)[idx] = o;
}

// ------------------------------- launch --------------------------------------
extern "C" void kernel_launch(void* const* d_in, const int* in_sizes, int n_in,
                              void* d_out, int out_size) {
    const float* x            = (const float*)d_in[0];
    const float* mixer_norm_w = (const float*)d_in[1];
    const float* in_proj_w    = (const float*)d_in[2];
    const float* conv_w       = (const float*)d_in[3];
    const float* conv_b       = (const float*)d_in[4];
    const float* x_proj_w     = (const float*)d_in[5];
    const float* dt_proj_w    = (const float*)d_in[6];
    const float* dt_proj_b    = (const float*)d_in[7];
    const float* A_log        = (const float*)d_in[8];
    const float* Dv           = (const float*)d_in[9];
    const float* out_proj_w   = (const float*)d_in[10];
    const float* mlp_norm_w   = (const float*)d_in[11];
    const float* gate_w       = (const float*)d_in[12];
    const float* up_w         = (const float*)d_in[13];
    const float* down_w       = (const float*)d_in[14];
    float* out = (float*)d_out;

    __half *h, *proj_h, *xi, *sp_h, *y_h, *act;
    float *sp, *dt, *y, *x2;
    __half *w_in, *w_xp, *w_dt, *w_out, *w_gate, *w_up, *w_down;
    cudaGetSymbolAddress((void**)&h, g_h);
    cudaGetSymbolAddress((void**)&proj_h, g_proj_h);
    cudaGetSymbolAddress((void**)&xi, g_xi);
    cudaGetSymbolAddress((void**)&sp, g_sp);
    cudaGetSymbolAddress((void**)&sp_h, g_sp_h);
    cudaGetSymbolAddress((void**)&dt, g_dt);
    cudaGetSymbolAddress((void**)&y, g_y);
    cudaGetSymbolAddress((void**)&y_h, g_y_h);
    cudaGetSymbolAddress((void**)&x2, g_x2);
    cudaGetSymbolAddress((void**)&act, g_act);
    cudaGetSymbolAddress((void**)&w_in, g_w_in);
    cudaGetSymbolAddress((void**)&w_xp, g_w_xp);
    cudaGetSymbolAddress((void**)&w_dt, g_w_dt);
    cudaGetSymbolAddress((void**)&w_out, g_w_out);
    cudaGetSymbolAddress((void**)&w_gate, g_w_gate);
    cudaGetSymbolAddress((void**)&w_up, g_w_up);
    cudaGetSymbolAddress((void**)&w_down, g_w_down);

    cudaFuncSetAttribute(hgemm, cudaFuncAttributeMaxDynamicSharedMemorySize,
                         GEMM_SMEM);

    to_half_perm_kernel<<<4096 * H_ / 256, 256>>>(in_proj_w, w_in, 4096 * H_);
    to_half_perm_kernel<<<96 * I_ / 256, 256>>>(x_proj_w, w_xp, 96 * I_);
    to_half_perm_kernel<<<I_ * R_ / 256, 256>>>(dt_proj_w, w_dt, I_ * R_);
    to_half_perm_kernel<<<H_ * I_ / 256, 256>>>(out_proj_w, w_out, H_ * I_);
    to_half_perm_kernel<<<M_MLP * H_ / 256, 256>>>(gate_w, w_gate, M_MLP * H_);
    to_half_perm_kernel<<<M_MLP * H_ / 256, 256>>>(up_w, w_up, M_MLP * H_);
    to_half_perm_kernel<<<H_ * M_MLP / 256, 256>>>(down_w, w_down, H_ * M_MLP);

    rmsnorm_kernel<<<BT_, 256>>>(x, mixer_norm_w, h);
    // proj_h = h @ in_proj^T   (16384 x 4096 x 1024), half out
    hgemm<<<dim3(32, 128), 256, GEMM_SMEM>>>(h, H_, w_in, nullptr, nullptr,
                                             nullptr, proj_h, 4096, H_, 0, 4096);
    conv_silu_kernel<<<BT_ * 512 / 256, 256>>>(proj_h, conv_w, conv_b, xi);
    // sp = xi @ x_proj^T     (16384 x 96 x 2048), fp32 + half out
    hgemm<<<dim3(1, 128), 256, GEMM_SMEM>>>(xi, I_, w_xp, nullptr, nullptr, sp,
                                            sp_h, 96, I_, 0, 96);
    // dt = softplus(sp[:,:64] @ dt_proj^T + b)   (16384 x 2048 x 64)
    hgemm<<<dim3(16, 128), 256, GEMM_SMEM>>>(sp_h, 96, w_dt, dt_proj_b, nullptr,
                                             dt, nullptr, I_, R_, 1, I_);
    // scan -> y (fp32)
    scan_kernel<<<(B_ * I_) / 16, 256>>>(dt, sp, xi, A_log, y);
    // y_h = half((y + xi*D) * silu(gate))
    ypost_kernel<<<BT_ * 512 / 256, 256>>>(y, xi, Dv, proj_h, y_h);
    // x2 = x + y @ out_proj^T   (16384 x 1024 x 2048)
    hgemm<<<dim3(8, 128), 256, GEMM_SMEM>>>(y_h, I_, w_out, x, nullptr, x2,
                                            nullptr, H_, I_, 2, H_);
    rmsnorm_kernel<<<BT_, 256>>>(x2, mlp_norm_w, h);
    // gate(half) = h @ gate_w^T   (16384 x 2816 x 1024)
    hgemm<<<dim3(22, 128), 256, GEMM_SMEM>>>(h, H_, w_gate, nullptr, nullptr,
                                             nullptr, proj_h, M_MLP, H_, 0,
                                             M_MLP);
    // act = half(silu(gate) * (h @ up_w^T))
    hgemm<<<dim3(22, 128), 256, GEMM_SMEM>>>(h, H_, w_up, nullptr, proj_h,
                                             nullptr, act, M_MLP, H_, 3, M_MLP);
    // out = x2 + act @ down_w^T   (16384 x 1024 x 2816)
    hgemm<<<dim3(8, 128), 256, GEMM_SMEM>>>(act, M_MLP, w_down, x2, nullptr,
                                            out, nullptr, H_, M_MLP, 2, H_);
}

// round 13
// speedup vs baseline: 1.8695x; 1.2388x over previous
#include <cuda_runtime.h>
#include <cuda_fp16.h>
#include <cstdint>

#define BT_ 16384
#define T_ 2048
#define B_ 8
#define H_ 1024
#define I_ 2048
#define N_SSM 16
#define R_ 64
#define M_MLP 2816

// ------------------------- scratch (device globals) --------------------------
__device__ __half g_h[BT_ * H_];        // rmsnorm out (half, GEMM A)
__device__ __half g_proj_h[BT_ * 4096]; // in_proj out / MLP gate out (half)
__device__ __half g_xi[BT_ * I_];       // conv+silu out (half)
__device__ float  g_sp[BT_ * 96];       // x_proj out fp32 (scan B/C)
__device__ __half g_sp_h[BT_ * 96];     // x_proj out half (dt GEMM A)
__device__ float  g_dt[BT_ * I_];       // softplus dt (fp32, scan)
__device__ float  g_y[BT_ * I_];        // scan out fp32
__device__ __half g_y_h[BT_ * I_];      // gated y half (out_proj A)
__device__ float  g_x2[BT_ * H_];       // mixer residual out
__device__ __half g_act[BT_ * M_MLP];   // silu(gate)*up (half, down A)
// weights: fp16, true k order (ldmatrix gathers fragments)
__device__ __half g_w_in[4096 * H_];
__device__ __half g_w_xp[96 * I_];
__device__ __half g_w_dt[I_ * R_];
__device__ __half g_w_out[H_ * I_];
__device__ __half g_w_gate[M_MLP * H_];
__device__ __half g_w_up[M_MLP * H_];
__device__ __half g_w_down[H_ * M_MLP];

__device__ __forceinline__ float siluf(float g) {
    return g * (1.0f / (1.0f + __expf(-g)));
}
__device__ __forceinline__ uint32_t smem_u32(const void* p) {
    return (uint32_t)__cvta_generic_to_shared(p);
}
__device__ __forceinline__ void cp16(uint32_t dst, const void* src) {
    asm volatile("cp.async.cg.shared.global [%0], [%1], 16;" ::"r"(dst), "l"(src));
}
#define CP_COMMIT() asm volatile("cp.async.commit_group;" ::: "memory")
#define CP_WAIT2() asm volatile("cp.async.wait_group 2;" ::: "memory")

// mma.sync m16n8k16 f16 -> f32 accum
#define MMA16(d, a0, a1, a2, a3, b0, b1)                                       \
    asm volatile(                                                              \
        "mma.sync.aligned.m16n8k16.row.col.f32.f16.f16.f32 "                   \
        "{%0,%1,%2,%3},{%4,%5,%6,%7},{%8,%9},{%0,%1,%2,%3};"                   \
        : "+f"((d)[0]), "+f"((d)[1]), "+f"((d)[2]), "+f"((d)[3])               \
        : "r"(a0), "r"(a1), "r"(a2), "r"(a3), "r"(b0), "r"(b1))

#define LDSM4(r, addr)                                                         \
    asm volatile(                                                              \
        "ldmatrix.sync.aligned.m8n8.x4.shared.b16 {%0,%1,%2,%3}, [%4];"        \
        : "=r"((r)[0]), "=r"((r)[1]), "=r"((r)[2]), "=r"((r)[3])               \
        : "r"(addr))

// ------------------------- fp16 mma.sync GEMM --------------------------------
// C[M,N] = A[M,K] @ W[N,K]^T, both half K-major TRUE order in gmem.
// BM=BN=128, BK=32, 4 stages, 8 warps (2m x 4n), warp tile 64x32, 2 CTAs/SM.
// Smem: row = 32 halfs = 4 x 16B chunks, chunk swizzle c' = c ^ ((row>>1)&3).
// Copies: plain 16B cp.async (4/thread/stage). Fragments: ldmatrix.x4
// (A: 2 per mi covering k0-15/k16-31; B: 1 per ni covering all BK=32).
// mode 0: C fp32 (if C) and/or Ch half (if Ch); 1: softplus(acc+aux[n])->C;
// 2: acc+aux[m*N+n]->C; 3: half(acc*silu(auxh[m*N+n]))->Ch
#define STAGES 4
#define STG_BYTES 16384  // A 8KB + B 8KB
#define GEMM_SMEM (STAGES * STG_BYTES)  // 64 KB

__global__ __launch_bounds__(256, 2) void hgemm(
    const __half* __restrict__ A, int lda, const __half* __restrict__ W,
    const float* __restrict__ aux, const __half* __restrict__ auxh,
    float* __restrict__ C, __half* __restrict__ Ch, int N, int K, int mode,
    int n_valid) {
    extern __shared__ uint32_t sm[];
    const uint32_t smb = smem_u32(sm);
    const int tid = threadIdx.x;
    const int lane = tid & 31, wid = tid >> 5;
    const int wm = wid & 1, wn = wid >> 1;
    const int qr = lane >> 2, qc = lane & 3;
    const int g = lane >> 3, lr = lane & 7;
    const int bm = blockIdx.y * 128, bn = blockIdx.x * 128;
    const int nk = K >> 5;

    // precomputed ldmatrix byte offsets within one stage
    uint32_t aoff0[4], aoff1[4], boff[4];
#pragma unroll
    for (int mi = 0; mi < 4; mi++) {
        int row = wm * 64 + mi * 16 + (g & 1) * 8 + lr;
        int f = (row >> 1) & 3;
        aoff0[mi] = row * 64 + (((g >> 1) ^ f) << 4);
        aoff1[mi] = row * 64 + (((2 + (g >> 1)) ^ f) << 4);
    }
#pragma unroll
    for (int ni = 0; ni < 4; ni++) {
        int row = wn * 32 + ni * 8 + lr;
        int f = (row >> 1) & 3;
        boff[ni] = 8192 + row * 64 + ((g ^ f) << 4);
    }

    float acc[4][4][4];
#pragma unroll
    for (int mi = 0; mi < 4; mi++)
#pragma unroll
        for (int ni = 0; ni < 4; ni++)
#pragma unroll
            for (int q = 0; q < 4; q++) acc[mi][ni][q] = 0.f;

    auto load_stage = [&](int s, int kt) {
        uint32_t sAb = smb + s * STG_BYTES;
        uint32_t sBb = sAb + 8192;
#pragma unroll
        for (int i = 0; i < 2; i++) {
            int ch = tid + i * 256;       // 512 chunks
            int r = ch >> 2, c = ch & 3;
            int cs = c ^ ((r >> 1) & 3);
            cp16(sAb + r * 64 + cs * 16,
                 A + (size_t)(bm + r) * lda + kt * 32 + c * 8);
        }
#pragma unroll
        for (int i = 0; i < 2; i++) {
            int ch = tid + i * 256;
            int r = ch >> 2, c = ch & 3;
            int cs = c ^ ((r >> 1) & 3);
            if (bn + r < n_valid)
                cp16(sBb + r * 64 + cs * 16,
                     W + (size_t)(bn + r) * (size_t)K + kt * 32 + c * 8);
        }
    };

    for (int s = 0; s < STAGES - 1; s++) {
        if (s < nk) load_stage(s, s);
        CP_COMMIT();
    }

    for (int kt = 0; kt < nk; kt++) {
        CP_WAIT2();
        __syncthreads();
        int pf = kt + STAGES - 1;
        if (pf < nk) load_stage(pf & 3, pf);
        CP_COMMIT();

        uint32_t sb = smb + (kt & 3) * STG_BYTES;
        uint32_t a0r[4][4], a1r[4][4], br[4][4];
#pragma unroll
        for (int ni = 0; ni < 4; ni++) LDSM4(br[ni], sb + boff[ni]);
#pragma unroll
        for (int mi = 0; mi < 4; mi++) {
            LDSM4(a0r[mi], sb + aoff0[mi]);
            LDSM4(a1r[mi], sb + aoff1[mi]);
        }
#pragma unroll
        for (int mi = 0; mi < 4; mi++)
#pragma unroll
            for (int ni = 0; ni < 4; ni++) {
                MMA16(acc[mi][ni], a0r[mi][0], a0r[mi][1], a0r[mi][2],
                      a0r[mi][3], br[ni][0], br[ni][1]);
                MMA16(acc[mi][ni], a1r[mi][0], a1r[mi][1], a1r[mi][2],
                      a1r[mi][3], br[ni][2], br[ni][3]);
            }
    }

    // epilogue: thread holds (r0,c0),(r0,c0+1),(r0+8,c0),(r0+8,c0+1) per tile
#pragma unroll
    for (int mi = 0; mi < 4; mi++) {
#pragma unroll
        for (int ni = 0; ni < 4; ni++) {
            int r0 = bm + wm * 64 + mi * 16 + qr;
            int c0 = bn + wn * 32 + ni * 8 + 2 * qc;
            if (c0 >= n_valid) continue;
            float v00 = acc[mi][ni][0], v01 = acc[mi][ni][1];
            float v10 = acc[mi][ni][2], v11 = acc[mi][ni][3];
            size_t g0 = (size_t)r0 * (size_t)N + c0;
            size_t g1 = g0 + (size_t)8 * N;
            if (mode == 1) {
                float b0 = __ldg(aux + c0), b1 = __ldg(aux + c0 + 1);
                float z;
                z = v00 + b0; v00 = fmaxf(z, 0.f) + log1pf(__expf(-fabsf(z)));
                z = v01 + b1; v01 = fmaxf(z, 0.f) + log1pf(__expf(-fabsf(z)));
                z = v10 + b0; v10 = fmaxf(z, 0.f) + log1pf(__expf(-fabsf(z)));
                z = v11 + b1; v11 = fmaxf(z, 0.f) + log1pf(__expf(-fabsf(z)));
                *(float2*)(C + g0) = make_float2(v00, v01);
                *(float2*)(C + g1) = make_float2(v10, v11);
            } else if (mode == 2) {
                float2 r0v = *(const float2*)(aux + g0);
                float2 r1v = *(const float2*)(aux + g1);
                *(float2*)(C + g0) = make_float2(v00 + r0v.x, v01 + r0v.y);
                *(float2*)(C + g1) = make_float2(v10 + r1v.x, v11 + r1v.y);
            } else if (mode == 3) {
                __half2 a0v = *(const __half2*)(auxh + g0);
                __half2 a1v = *(const __half2*)(auxh + g1);
                *(__half2*)(Ch + g0) = __floats2half2_rn(
                    v00 * siluf(__low2float(a0v)), v01 * siluf(__high2float(a0v)));
                *(__half2*)(Ch + g1) = __floats2half2_rn(
                    v10 * siluf(__low2float(a1v)), v11 * siluf(__high2float(a1v)));
            } else {
                if (C != nullptr) {
                    *(float2*)(C + g0) = make_float2(v00, v01);
                    *(float2*)(C + g1) = make_float2(v10, v11);
                }
                if (Ch != nullptr) {
                    *(__half2*)(Ch + g0) = __floats2half2_rn(v00, v01);
                    *(__half2*)(Ch + g1) = __floats2half2_rn(v10, v11);
                }
            }
        }
    }
}

// --------------------------- fp32 -> fp16 convert ----------------------------
__global__ void to_half_kernel(const float* __restrict__ src,
                               __half* __restrict__ dst, int n4) {
    int i = blockIdx.x * 256 + threadIdx.x;
    if (i < n4) {
        float4 v = ((const float4*)src)[i];
        __half2 h0 = __floats2half2_rn(v.x, v.y);
        __half2 h1 = __floats2half2_rn(v.z, v.w);
        uint2 o;
        o.x = *(uint32_t*)&h0;
        o.y = *(uint32_t*)&h1;
        ((uint2*)dst)[i] = o;
    }
}

// ------------------------------- rmsnorm (-> half) ---------------------------
__global__ void rmsnorm_kernel(const float* __restrict__ x,
                               const float* __restrict__ w,
                               __half* __restrict__ out) {
    int row = blockIdx.x;
    int t = threadIdx.x;
    const float4* xr = (const float4*)(x + (size_t)row * H_);
    float4 v = xr[t];
    float ss = v.x * v.x + v.y * v.y + v.z * v.z + v.w * v.w;
#pragma unroll
    for (int o = 16; o > 0; o >>= 1) ss += __shfl_down_sync(0xffffffffu, ss, o);
    __shared__ float red[8];
    if ((t & 31) == 0) red[t >> 5] = ss;
    __syncthreads();
    float tot = red[0] + red[1] + red[2] + red[3] + red[4] + red[5] + red[6] + red[7];
    float scale = rsqrtf(tot * (1.0f / (float)H_) + 1e-5f);
    float4 wv = ((const float4*)w)[t];
    __half2 h0 = __floats2half2_rn(v.x * scale * wv.x, v.y * scale * wv.y);
    __half2 h1 = __floats2half2_rn(v.z * scale * wv.z, v.w * scale * wv.w);
    uint2 o;
    o.x = *(uint32_t*)&h0;
    o.y = *(uint32_t*)&h1;
    ((uint2*)(out + (size_t)row * H_))[t] = o;
}

// ---------------- causal depthwise conv + silu (half in, half out) -----------
__global__ void conv_silu_kernel(const __half* __restrict__ proj,
                                 const float* __restrict__ cw,
                                 const float* __restrict__ cb,
                                 __half* __restrict__ xi) {
    int idx = blockIdx.x * blockDim.x + threadIdx.x;
    int i4 = idx & 511;
    int bt = idx >> 9;
    int t = bt & (T_ - 1);
    const float4* cwv = (const float4*)cw;
    float w[4][4];
#pragma unroll
    for (int c = 0; c < 4; c++) {
        float4 tmp = cwv[i4 * 4 + c];
        w[c][0] = tmp.x; w[c][1] = tmp.y; w[c][2] = tmp.z; w[c][3] = tmp.w;
    }
    float4 cbv = ((const float4*)cb)[i4];
    float acc[4] = {cbv.x, cbv.y, cbv.z, cbv.w};
    const __half* base = proj + (size_t)bt * 4096 + i4 * 4;
#pragma unroll
    for (int k = 0; k < 4; ++k) {
        int back = 3 - k;
        if (t >= back) {
            uint2 pr = *(const uint2*)(base - (size_t)back * 4096);
            __half2 p0 = *(__half2*)&pr.x;
            __half2 p1 = *(__half2*)&pr.y;
            acc[0] += __low2float(p0) * w[0][k];
            acc[1] += __high2float(p0) * w[1][k];
            acc[2] += __low2float(p1) * w[2][k];
            acc[3] += __high2float(p1) * w[3][k];
        }
    }
    __half2 h0 = __floats2half2_rn(siluf(acc[0]), siluf(acc[1]));
    __half2 h1 = __floats2half2_rn(siluf(acc[2]), siluf(acc[3]));
    uint2 o;
    o.x = *(uint32_t*)&h0;
    o.y = *(uint32_t*)&h1;
    ((uint2*)xi)[idx] = o;
}

// ------------------------------ selective scan -------------------------------
__global__ __launch_bounds__(256) void scan_kernel(
    const float* __restrict__ dt, const float* __restrict__ sp,
    const __half* __restrict__ xi, const float* __restrict__ A_log,
    float* __restrict__ y) {
    __shared__ float sBC[64][32];
    int tid = threadIdx.x;
    int warp = tid >> 5, lane = tid & 31;
    int half_ = lane >> 4, n = lane & 15;
    int chan = blockIdx.x * 16 + warp * 2 + half_;
    int b = chan >> 11;
    int i = chan & (I_ - 1);
    float A = -__expf(__ldg(A_log + i * N_SSM + n));
    size_t rowoff = (size_t)b * T_ * I_ + i;
    size_t spoff = (size_t)b * T_ * 96;
    float s = 0.f;

    for (int t0 = 0; t0 < T_; t0 += 64) {
        __syncthreads();
#pragma unroll
        for (int q = tid; q < 512; q += 256) {
            int r = q >> 3, c = (q & 7) << 2;
            *(float4*)&sBC[r][c] =
                *(const float4*)(sp + spoff + (size_t)(t0 + r) * 96 + 64 + c);
        }
        __syncthreads();
        size_t off = rowoff + (size_t)t0 * I_;
        for (int tl = 0; tl < 64; ++tl, off += I_) {
            float dtv = __ldg(dt + off);
            float xv = __half2float(__ldg(xi + off));
            float dA = __expf(dtv * A);
            s = fmaf(dA, s, dtv * xv * sBC[tl][n]);
            float yv = s * sBC[tl][16 + n];
            yv += __shfl_down_sync(0xffffffffu, yv, 8, 16);
            yv += __shfl_down_sync(0xffffffffu, yv, 4, 16);
            yv += __shfl_down_sync(0xffffffffu, yv, 2, 16);
            yv += __shfl_down_sync(0xffffffffu, yv, 1, 16);
            if (n == 0) y[off] = yv;
        }
    }
}

// --------------- y_h = half((y + xi*D) * silu(gate_half)) --------------------
__global__ void ypost_kernel(const float* __restrict__ y,
                             const __half* __restrict__ xi,
                             const float* __restrict__ D,
                             const __half* __restrict__ proj,
                             __half* __restrict__ yh) {
    size_t idx = (size_t)blockIdx.x * 256 + threadIdx.x;
    size_t i4 = idx & 511;
    size_t bt = idx >> 9;
    float4 yv = ((const float4*)y)[idx];
    uint2 xr = ((const uint2*)xi)[idx];
    __half2 x0 = *(__half2*)&xr.x;
    __half2 x1 = *(__half2*)&xr.y;
    float4 dv = ((const float4*)D)[i4];
    uint2 gr = *(const uint2*)(proj + bt * 4096 + I_ + i4 * 4);
    __half2 g0 = *(__half2*)&gr.x;
    __half2 g1 = *(__half2*)&gr.y;
    float o0 = (yv.x + __low2float(x0) * dv.x) * siluf(__low2float(g0));
    float o1 = (yv.y + __high2float(x0) * dv.y) * siluf(__high2float(g0));
    float o2 = (yv.z + __low2float(x1) * dv.z) * siluf(__low2float(g1));
    float o3 = (yv.w + __high2float(x1) * dv.w) * siluf(__high2float(g1));
    __half2 h0 = __floats2half2_rn(o0, o1);
    __half2 h1 = __floats2half2_rn(o2, o3);
    uint2 o;
    o.x = *(uint32_t*)&h0;
    o.y = *(uint32_t*)&h1;
    ((uint2*)yh)[idx] = o;
}

// ------------------------------- launch --------------------------------------
extern "C" void kernel_launch(void* const* d_in, const int* in_sizes, int n_in,
                              void* d_out, int out_size) {
    const float* x            = (const float*)d_in[0];
    const float* mixer_norm_w = (const float*)d_in[1];
    const float* in_proj_w    = (const float*)d_in[2];
    const float* conv_w       = (const float*)d_in[3];
    const float* conv_b       = (const float*)d_in[4];
    const float* x_proj_w     = (const float*)d_in[5];
    const float* dt_proj_w    = (const float*)d_in[6];
    const float* dt_proj_b    = (const float*)d_in[7];
    const float* A_log        = (const float*)d_in[8];
    const float* Dv           = (const float*)d_in[9];
    const float* out_proj_w   = (const float*)d_in[10];
    const float* mlp_norm_w   = (const float*)d_in[11];
    const float* gate_w       = (const float*)d_in[12];
    const float* up_w         = (const float*)d_in[13];
    const float* down_w       = (const float*)d_in[14];
    float* out = (float*)d_out;

    __half *h, *proj_h, *xi, *sp_h, *y_h, *act;
    float *sp, *dt, *y, *x2;
    __half *w_in, *w_xp, *w_dt, *w_out, *w_gate, *w_up, *w_down;
    cudaGetSymbolAddress((void**)&h, g_h);
    cudaGetSymbolAddress((void**)&proj_h, g_proj_h);
    cudaGetSymbolAddress((void**)&xi, g_xi);
    cudaGetSymbolAddress((void**)&sp, g_sp);
    cudaGetSymbolAddress((void**)&sp_h, g_sp_h);
    cudaGetSymbolAddress((void**)&dt, g_dt);
    cudaGetSymbolAddress((void**)&y, g_y);
    cudaGetSymbolAddress((void**)&y_h, g_y_h);
    cudaGetSymbolAddress((void**)&x2, g_x2);
    cudaGetSymbolAddress((void**)&act, g_act);
    cudaGetSymbolAddress((void**)&w_in, g_w_in);
    cudaGetSymbolAddress((void**)&w_xp, g_w_xp);
    cudaGetSymbolAddress((void**)&w_dt, g_w_dt);
    cudaGetSymbolAddress((void**)&w_out, g_w_out);
    cudaGetSymbolAddress((void**)&w_gate, g_w_gate);
    cudaGetSymbolAddress((void**)&w_up, g_w_up);
    cudaGetSymbolAddress((void**)&w_down, g_w_down);

    cudaFuncSetAttribute(hgemm, cudaFuncAttributeMaxDynamicSharedMemorySize,
                         GEMM_SMEM);

    to_half_kernel<<<4096, 256>>>(in_proj_w, w_in, 4096 * H_ / 4);
    to_half_kernel<<<192, 256>>>(x_proj_w, w_xp, 96 * I_ / 4);
    to_half_kernel<<<128, 256>>>(dt_proj_w, w_dt, I_ * R_ / 4);
    to_half_kernel<<<2048, 256>>>(out_proj_w, w_out, H_ * I_ / 4);
    to_half_kernel<<<2816, 256>>>(gate_w, w_gate, M_MLP * H_ / 4);
    to_half_kernel<<<2816, 256>>>(up_w, w_up, M_MLP * H_ / 4);
    to_half_kernel<<<2816, 256>>>(down_w, w_down, H_ * M_MLP / 4);

    rmsnorm_kernel<<<BT_, 256>>>(x, mixer_norm_w, h);
    // proj_h = h @ in_proj^T   (16384 x 4096 x 1024), half out
    hgemm<<<dim3(32, 128), 256, GEMM_SMEM>>>(h, H_, w_in, nullptr, nullptr,
                                             nullptr, proj_h, 4096, H_, 0, 4096);
    conv_silu_kernel<<<BT_ * 512 / 256, 256>>>(proj_h, conv_w, conv_b, xi);
    // sp = xi @ x_proj^T     (16384 x 96 x 2048), fp32 + half out
    hgemm<<<dim3(1, 128), 256, GEMM_SMEM>>>(xi, I_, w_xp, nullptr, nullptr, sp,
                                            sp_h, 96, I_, 0, 96);
    // dt = softplus(sp[:,:64] @ dt_proj^T + b)   (16384 x 2048 x 64)
    hgemm<<<dim3(16, 128), 256, GEMM_SMEM>>>(sp_h, 96, w_dt, dt_proj_b, nullptr,
                                             dt, nullptr, I_, R_, 1, I_);
    // scan -> y (fp32)
    scan_kernel<<<(B_ * I_) / 16, 256>>>(dt, sp, xi, A_log, y);
    // y_h = half((y + xi*D) * silu(gate))
    ypost_kernel<<<BT_ * 512 / 256, 256>>>(y, xi, Dv, proj_h, y_h);
    // x2 = x + y @ out_proj^T   (16384 x 1024 x 2048)
    hgemm<<<dim3(8, 128), 256, GEMM_SMEM>>>(y_h, I_, w_out, x, nullptr, x2,
                                            nullptr, H_, I_, 2, H_);
    rmsnorm_kernel<<<BT_, 256>>>(x2, mlp_norm_w, h);
    // gate(half) = h @ gate_w^T   (16384 x 2816 x 1024)
    hgemm<<<dim3(22, 128), 256, GEMM_SMEM>>>(h, H_, w_gate, nullptr, nullptr,
                                             nullptr, proj_h, M_MLP, H_, 0,
                                             M_MLP);
    // act = half(silu(gate) * (h @ up_w^T))
    hgemm<<<dim3(22, 128), 256, GEMM_SMEM>>>(h, H_, w_up, nullptr, proj_h,
                                             nullptr, act, M_MLP, H_, 3, M_MLP);
    // out = x2 + act @ down_w^T   (16384 x 1024 x 2816)
    hgemm<<<dim3(8, 128), 256, GEMM_SMEM>>>(act, M_MLP, w_down, x2, nullptr,
                                            out, nullptr, H_, M_MLP, 2, H_);
}

// round 14
// speedup vs baseline: 1.9367x; 1.0359x over previous
#include <cuda_runtime.h>
#include <cuda_fp16.h>
#include <cstdint>

#define BT_ 16384
#define T_ 2048
#define B_ 8
#define H_ 1024
#define I_ 2048
#define N_SSM 16
#define R_ 64
#define M_MLP 2816

// ------------------------- scratch (device globals) --------------------------
__device__ __half g_h[BT_ * H_];        // rmsnorm out (half, GEMM A)
__device__ __half g_proj_h[BT_ * 4096]; // in_proj out / MLP gate out (half)
__device__ __half g_xi[BT_ * I_];       // conv+silu out (half)
__device__ float  g_sp[BT_ * 96];       // x_proj out fp32 (scan B/C)
__device__ __half g_sp_h[BT_ * 96];     // x_proj out half (dt GEMM A)
__device__ float  g_dt[BT_ * I_];       // softplus dt (fp32, scan)
__device__ __half g_yraw[BT_ * I_];     // scan raw y (half)
__device__ __half g_y_h[BT_ * I_];      // gated y half (out_proj A)
__device__ float  g_x2[BT_ * H_];       // mixer residual out
__device__ __half g_act[BT_ * M_MLP];   // silu(gate)*up (half, down A)
// weights: fp16, true k order (ldmatrix gathers fragments)
__device__ __half g_w_in[4096 * H_];
__device__ __half g_w_xp[96 * I_];
__device__ __half g_w_dt[I_ * R_];
__device__ __half g_w_out[H_ * I_];
__device__ __half g_w_gate[M_MLP * H_];
__device__ __half g_w_up[M_MLP * H_];
__device__ __half g_w_down[H_ * M_MLP];

__device__ __forceinline__ float siluf(float g) {
    return g * (1.0f / (1.0f + __expf(-g)));
}
__device__ __forceinline__ uint32_t smem_u32(const void* p) {
    return (uint32_t)__cvta_generic_to_shared(p);
}
__device__ __forceinline__ void cp16(uint32_t dst, const void* src) {
    asm volatile("cp.async.cg.shared.global [%0], [%1], 16;" ::"r"(dst), "l"(src));
}
#define CP_COMMIT() asm volatile("cp.async.commit_group;" ::: "memory")
#define CP_WAIT2() asm volatile("cp.async.wait_group 2;" ::: "memory")

// mma.sync m16n8k16 f16 -> f32 accum
#define MMA16(d, a0, a1, a2, a3, b0, b1)                                       \
    asm volatile(                                                              \
        "mma.sync.aligned.m16n8k16.row.col.f32.f16.f16.f32 "                   \
        "{%0,%1,%2,%3},{%4,%5,%6,%7},{%8,%9},{%0,%1,%2,%3};"                   \
        : "+f"((d)[0]), "+f"((d)[1]), "+f"((d)[2]), "+f"((d)[3])               \
        : "r"(a0), "r"(a1), "r"(a2), "r"(a3), "r"(b0), "r"(b1))

#define LDSM4(r, addr)                                                         \
    asm volatile(                                                              \
        "ldmatrix.sync.aligned.m8n8.x4.shared.b16 {%0,%1,%2,%3}, [%4];"        \
        : "=r"((r)[0]), "=r"((r)[1]), "=r"((r)[2]), "=r"((r)[3])               \
        : "r"(addr))

// ------------------------- fp16 mma.sync GEMM (R13 proven) -------------------
// C[M,N] = A[M,K] @ W[N,K]^T, both half K-major TRUE order.
// BM=BN=128, BK=32, 4 stages, 8 warps (2m x 4n), warp tile 64x32, 2 CTAs/SM.
// Smem: row = 32 halfs = 4 x 16B chunks, chunk swizzle c' = c ^ ((row>>1)&3).
// Copies: 16B cp.async (4/thread/stage). Fragments: ldmatrix.x4.
// mode 0: C fp32 (if C) and/or Ch half (if Ch); 1: softplus(acc+aux[n])->C;
// 2: acc+aux[m*N+n]->C; 3: half(acc*silu(auxh[m*N+n]))->Ch
#define STAGES 4
#define STG_BYTES 16384
#define GEMM_SMEM (STAGES * STG_BYTES)  // 64 KB

__global__ __launch_bounds__(256, 2) void hgemm(
    const __half* __restrict__ A, int lda, const __half* __restrict__ W,
    const float* __restrict__ aux, const __half* __restrict__ auxh,
    float* __restrict__ C, __half* __restrict__ Ch, int N, int K, int mode,
    int n_valid) {
    extern __shared__ uint32_t sm[];
    const uint32_t smb = smem_u32(sm);
    const int tid = threadIdx.x;
    const int lane = tid & 31, wid = tid >> 5;
    const int wm = wid & 1, wn = wid >> 1;
    const int qr = lane >> 2, qc = lane & 3;
    const int g = lane >> 3, lr = lane & 7;
    const int bm = blockIdx.y * 128, bn = blockIdx.x * 128;
    const int nk = K >> 5;

    uint32_t aoff0[4], aoff1[4], boff[4];
#pragma unroll
    for (int mi = 0; mi < 4; mi++) {
        int row = wm * 64 + mi * 16 + (g & 1) * 8 + lr;
        int f = (row >> 1) & 3;
        aoff0[mi] = row * 64 + (((g >> 1) ^ f) << 4);
        aoff1[mi] = row * 64 + (((2 + (g >> 1)) ^ f) << 4);
    }
#pragma unroll
    for (int ni = 0; ni < 4; ni++) {
        int row = wn * 32 + ni * 8 + lr;
        int f = (row >> 1) & 3;
        boff[ni] = 8192 + row * 64 + ((g ^ f) << 4);
    }

    float acc[4][4][4];
#pragma unroll
    for (int mi = 0; mi < 4; mi++)
#pragma unroll
        for (int ni = 0; ni < 4; ni++)
#pragma unroll
            for (int q = 0; q < 4; q++) acc[mi][ni][q] = 0.f;

    auto load_stage = [&](int s, int kt) {
        uint32_t sAb = smb + s * STG_BYTES;
        uint32_t sBb = sAb + 8192;
#pragma unroll
        for (int i = 0; i < 2; i++) {
            int ch = tid + i * 256;
            int r = ch >> 2, c = ch & 3;
            int cs = c ^ ((r >> 1) & 3);
            cp16(sAb + r * 64 + cs * 16,
                 A + (size_t)(bm + r) * lda + kt * 32 + c * 8);
        }
#pragma unroll
        for (int i = 0; i < 2; i++) {
            int ch = tid + i * 256;
            int r = ch >> 2, c = ch & 3;
            int cs = c ^ ((r >> 1) & 3);
            if (bn + r < n_valid)
                cp16(sBb + r * 64 + cs * 16,
                     W + (size_t)(bn + r) * (size_t)K + kt * 32 + c * 8);
        }
    };

    for (int s = 0; s < STAGES - 1; s++) {
        if (s < nk) load_stage(s, s);
        CP_COMMIT();
    }

    for (int kt = 0; kt < nk; kt++) {
        CP_WAIT2();
        __syncthreads();
        int pf = kt + STAGES - 1;
        if (pf < nk) load_stage(pf & 3, pf);
        CP_COMMIT();

        uint32_t sb = smb + (kt & 3) * STG_BYTES;
        uint32_t a0r[4][4], a1r[4][4], br[4][4];
#pragma unroll
        for (int ni = 0; ni < 4; ni++) LDSM4(br[ni], sb + boff[ni]);
#pragma unroll
        for (int mi = 0; mi < 4; mi++) {
            LDSM4(a0r[mi], sb + aoff0[mi]);
            LDSM4(a1r[mi], sb + aoff1[mi]);
        }
#pragma unroll
        for (int mi = 0; mi < 4; mi++)
#pragma unroll
            for (int ni = 0; ni < 4; ni++) {
                MMA16(acc[mi][ni], a0r[mi][0], a0r[mi][1], a0r[mi][2],
                      a0r[mi][3], br[ni][0], br[ni][1]);
                MMA16(acc[mi][ni], a1r[mi][0], a1r[mi][1], a1r[mi][2],
                      a1r[mi][3], br[ni][2], br[ni][3]);
            }
    }

#pragma unroll
    for (int mi = 0; mi < 4; mi++) {
#pragma unroll
        for (int ni = 0; ni < 4; ni++) {
            int r0 = bm + wm * 64 + mi * 16 + qr;
            int c0 = bn + wn * 32 + ni * 8 + 2 * qc;
            if (c0 >= n_valid) continue;
            float v00 = acc[mi][ni][0], v01 = acc[mi][ni][1];
            float v10 = acc[mi][ni][2], v11 = acc[mi][ni][3];
            size_t g0 = (size_t)r0 * (size_t)N + c0;
            size_t g1 = g0 + (size_t)8 * N;
            if (mode == 1) {
                float b0 = __ldg(aux + c0), b1 = __ldg(aux + c0 + 1);
                float z;
                z = v00 + b0; v00 = fmaxf(z, 0.f) + log1pf(__expf(-fabsf(z)));
                z = v01 + b1; v01 = fmaxf(z, 0.f) + log1pf(__expf(-fabsf(z)));
                z = v10 + b0; v10 = fmaxf(z, 0.f) + log1pf(__expf(-fabsf(z)));
                z = v11 + b1; v11 = fmaxf(z, 0.f) + log1pf(__expf(-fabsf(z)));
                *(float2*)(C + g0) = make_float2(v00, v01);
                *(float2*)(C + g1) = make_float2(v10, v11);
            } else if (mode == 2) {
                float2 r0v = *(const float2*)(aux + g0);
                float2 r1v = *(const float2*)(aux + g1);
                *(float2*)(C + g0) = make_float2(v00 + r0v.x, v01 + r0v.y);
                *(float2*)(C + g1) = make_float2(v10 + r1v.x, v11 + r1v.y);
            } else if (mode == 3) {
                __half2 a0v = *(const __half2*)(auxh + g0);
                __half2 a1v = *(const __half2*)(auxh + g1);
                *(__half2*)(Ch + g0) = __floats2half2_rn(
                    v00 * siluf(__low2float(a0v)), v01 * siluf(__high2float(a0v)));
                *(__half2*)(Ch + g1) = __floats2half2_rn(
                    v10 * siluf(__low2float(a1v)), v11 * siluf(__high2float(a1v)));
            } else {
                if (C != nullptr) {
                    *(float2*)(C + g0) = make_float2(v00, v01);
                    *(float2*)(C + g1) = make_float2(v10, v11);
                }
                if (Ch != nullptr) {
                    *(__half2*)(Ch + g0) = __floats2half2_rn(v00, v01);
                    *(__half2*)(Ch + g1) = __floats2half2_rn(v10, v11);
                }
            }
        }
    }
}

// --------------------------- fp32 -> fp16 convert ----------------------------
__global__ void to_half_kernel(const float* __restrict__ src,
                               __half* __restrict__ dst, int n4) {
    int i = blockIdx.x * 256 + threadIdx.x;
    if (i < n4) {
        float4 v = ((const float4*)src)[i];
        __half2 h0 = __floats2half2_rn(v.x, v.y);
        __half2 h1 = __floats2half2_rn(v.z, v.w);
        uint2 o;
        o.x = *(uint32_t*)&h0;
        o.y = *(uint32_t*)&h1;
        ((uint2*)dst)[i] = o;
    }
}

// ------------------------------- rmsnorm (-> half) ---------------------------
__global__ void rmsnorm_kernel(const float* __restrict__ x,
                               const float* __restrict__ w,
                               __half* __restrict__ out) {
    int row = blockIdx.x;
    int t = threadIdx.x;
    const float4* xr = (const float4*)(x + (size_t)row * H_);
    float4 v = xr[t];
    float ss = v.x * v.x + v.y * v.y + v.z * v.z + v.w * v.w;
#pragma unroll
    for (int o = 16; o > 0; o >>= 1) ss += __shfl_down_sync(0xffffffffu, ss, o);
    __shared__ float red[8];
    if ((t & 31) == 0) red[t >> 5] = ss;
    __syncthreads();
    float tot = red[0] + red[1] + red[2] + red[3] + red[4] + red[5] + red[6] + red[7];
    float scale = rsqrtf(tot * (1.0f / (float)H_) + 1e-5f);
    float4 wv = ((const float4*)w)[t];
    __half2 h0 = __floats2half2_rn(v.x * scale * wv.x, v.y * scale * wv.y);
    __half2 h1 = __floats2half2_rn(v.z * scale * wv.z, v.w * scale * wv.w);
    uint2 o;
    o.x = *(uint32_t*)&h0;
    o.y = *(uint32_t*)&h1;
    ((uint2*)(out + (size_t)row * H_))[t] = o;
}

// ---------------- causal depthwise conv + silu (half in, half out) -----------
__global__ void conv_silu_kernel(const __half* __restrict__ proj,
                                 const float* __restrict__ cw,
                                 const float* __restrict__ cb,
                                 __half* __restrict__ xi) {
    int idx = blockIdx.x * blockDim.x + threadIdx.x;
    int i4 = idx & 511;
    int bt = idx >> 9;
    int t = bt & (T_ - 1);
    const float4* cwv = (const float4*)cw;
    float w[4][4];
#pragma unroll
    for (int c = 0; c < 4; c++) {
        float4 tmp = cwv[i4 * 4 + c];
        w[c][0] = tmp.x; w[c][1] = tmp.y; w[c][2] = tmp.z; w[c][3] = tmp.w;
    }
    float4 cbv = ((const float4*)cb)[i4];
    float acc[4] = {cbv.x, cbv.y, cbv.z, cbv.w};
    const __half* base = proj + (size_t)bt * 4096 + i4 * 4;
#pragma unroll
    for (int k = 0; k < 4; ++k) {
        int back = 3 - k;
        if (t >= back) {
            uint2 pr = *(const uint2*)(base - (size_t)back * 4096);
            __half2 p0 = *(__half2*)&pr.x;
            __half2 p1 = *(__half2*)&pr.y;
            acc[0] += __low2float(p0) * w[0][k];
            acc[1] += __high2float(p0) * w[1][k];
            acc[2] += __low2float(p1) * w[2][k];
            acc[3] += __high2float(p1) * w[3][k];
        }
    }
    __half2 h0 = __floats2half2_rn(siluf(acc[0]), siluf(acc[1]));
    __half2 h1 = __floats2half2_rn(siluf(acc[2]), siluf(acc[3]));
    uint2 o;
    o.x = *(uint32_t*)&h0;
    o.y = *(uint32_t*)&h1;
    ((uint2*)xi)[idx] = o;
}

// ------------------------------ selective scan -------------------------------
// 4 channels/warp (8 lanes each, 2 states/lane). Raw y emitted as half.
// A pre-scaled by log2(e) so dA = exp2f(dt * A').
__global__ __launch_bounds__(256) void scan_kernel(
    const float* __restrict__ dt, const float* __restrict__ sp,
    const __half* __restrict__ xi, const float* __restrict__ A_log,
    __half* __restrict__ yraw) {
    __shared__ float sBC[64][32];
    int tid = threadIdx.x;
    int warp = tid >> 5, lane = tid & 31;
    int q = lane >> 3, ln = lane & 7;
    int chan = blockIdx.x * 32 + warp * 4 + q;
    int b = chan >> 11;
    int i = chan & (I_ - 1);
    const float LOG2E = 1.4426950408889634f;
    float A0 = -__expf(__ldg(A_log + i * N_SSM + ln)) * LOG2E;
    float A1 = -__expf(__ldg(A_log + i * N_SSM + ln + 8)) * LOG2E;
    size_t rowoff = (size_t)b * T_ * I_ + i;
    size_t spoff = (size_t)b * T_ * 96;
    float s0 = 0.f, s1 = 0.f;

    for (int t0 = 0; t0 < T_; t0 += 64) {
        __syncthreads();
#pragma unroll
        for (int p = tid; p < 512; p += 256) {
            int r = p >> 3, c = (p & 7) << 2;
            *(float4*)&sBC[r][c] =
                *(const float4*)(sp + spoff + (size_t)(t0 + r) * 96 + 64 + c);
        }
        __syncthreads();
        size_t off = rowoff + (size_t)t0 * I_;
        for (int tl = 0; tl < 64; ++tl, off += I_) {
            float dtv = __ldg(dt + off);
            float xv = __half2float(__ldg(xi + off));
            float dA0 = exp2f(dtv * A0);
            float dA1 = exp2f(dtv * A1);
            float dx = dtv * xv;
            s0 = fmaf(dA0, s0, dx * sBC[tl][ln]);
            s1 = fmaf(dA1, s1, dx * sBC[tl][ln + 8]);
            float yv = fmaf(s1, sBC[tl][24 + ln], s0 * sBC[tl][16 + ln]);
            yv += __shfl_down_sync(0xffffffffu, yv, 4, 8);
            yv += __shfl_down_sync(0xffffffffu, yv, 2, 8);
            yv += __shfl_down_sync(0xffffffffu, yv, 1, 8);
            if (ln == 0) yraw[off] = __float2half_rn(yv);
        }
    }
}

// --------------- y_h = half((y_raw + xi*D) * silu(gate_half)) ----------------
__global__ void ypost_kernel(const __half* __restrict__ yraw,
                             const __half* __restrict__ xi,
                             const float* __restrict__ D,
                             const __half* __restrict__ proj,
                             __half* __restrict__ yh) {
    size_t idx = (size_t)blockIdx.x * 256 + threadIdx.x;
    size_t i4 = idx & 511;
    size_t bt = idx >> 9;
    uint2 yr = ((const uint2*)yraw)[idx];
    __half2 y0 = *(__half2*)&yr.x;
    __half2 y1 = *(__half2*)&yr.y;
    uint2 xr = ((const uint2*)xi)[idx];
    __half2 x0 = *(__half2*)&xr.x;
    __half2 x1 = *(__half2*)&xr.y;
    float4 dv = ((const float4*)D)[i4];
    uint2 gr = *(const uint2*)(proj + bt * 4096 + I_ + i4 * 4);
    __half2 g0 = *(__half2*)&gr.x;
    __half2 g1 = *(__half2*)&gr.y;
    float o0 = (__low2float(y0) + __low2float(x0) * dv.x) * siluf(__low2float(g0));
    float o1 = (__high2float(y0) + __high2float(x0) * dv.y) * siluf(__high2float(g0));
    float o2 = (__low2float(y1) + __low2float(x1) * dv.z) * siluf(__low2float(g1));
    float o3 = (__high2float(y1) + __high2float(x1) * dv.w) * siluf(__high2float(g1));
    __half2 h0 = __floats2half2_rn(o0, o1);
    __half2 h1 = __floats2half2_rn(o2, o3);
    uint2 o;
    o.x = *(uint32_t*)&h0;
    o.y = *(uint32_t*)&h1;
    ((uint2*)yh)[idx] = o;
}

// ------------------------------- launch --------------------------------------
extern "C" void kernel_launch(void* const* d_in, const int* in_sizes, int n_in,
                              void* d_out, int out_size) {
    const float* x            = (const float*)d_in[0];
    const float* mixer_norm_w = (const float*)d_in[1];
    const float* in_proj_w    = (const float*)d_in[2];
    const float* conv_w       = (const float*)d_in[3];
    const float* conv_b       = (const float*)d_in[4];
    const float* x_proj_w     = (const float*)d_in[5];
    const float* dt_proj_w    = (const float*)d_in[6];
    const float* dt_proj_b    = (const float*)d_in[7];
    const float* A_log        = (const float*)d_in[8];
    const float* Dv           = (const float*)d_in[9];
    const float* out_proj_w   = (const float*)d_in[10];
    const float* mlp_norm_w   = (const float*)d_in[11];
    const float* gate_w       = (const float*)d_in[12];
    const float* up_w         = (const float*)d_in[13];
    const float* down_w       = (const float*)d_in[14];
    float* out = (float*)d_out;

    __half *h, *proj_h, *xi, *sp_h, *yraw, *y_h, *act;
    float *sp, *dt, *x2;
    __half *w_in, *w_xp, *w_dt, *w_out, *w_gate, *w_up, *w_down;
    cudaGetSymbolAddress((void**)&h, g_h);
    cudaGetSymbolAddress((void**)&proj_h, g_proj_h);
    cudaGetSymbolAddress((void**)&xi, g_xi);
    cudaGetSymbolAddress((void**)&sp, g_sp);
    cudaGetSymbolAddress((void**)&sp_h, g_sp_h);
    cudaGetSymbolAddress((void**)&dt, g_dt);
    cudaGetSymbolAddress((void**)&yraw, g_yraw);
    cudaGetSymbolAddress((void**)&y_h, g_y_h);
    cudaGetSymbolAddress((void**)&x2, g_x2);
    cudaGetSymbolAddress((void**)&act, g_act);
    cudaGetSymbolAddress((void**)&w_in, g_w_in);
    cudaGetSymbolAddress((void**)&w_xp, g_w_xp);
    cudaGetSymbolAddress((void**)&w_dt, g_w_dt);
    cudaGetSymbolAddress((void**)&w_out, g_w_out);
    cudaGetSymbolAddress((void**)&w_gate, g_w_gate);
    cudaGetSymbolAddress((void**)&w_up, g_w_up);
    cudaGetSymbolAddress((void**)&w_down, g_w_down);

    cudaFuncSetAttribute(hgemm, cudaFuncAttributeMaxDynamicSharedMemorySize,
                         GEMM_SMEM);

    // Order chosen so the big in_proj GEMM is the 6th launch (ncu -s 5 -c 1).
    rmsnorm_kernel<<<BT_, 256>>>(x, mixer_norm_w, h);               // 1
    to_half_kernel<<<4096, 256>>>(in_proj_w, w_in, 4096 * H_ / 4);  // 2
    to_half_kernel<<<192, 256>>>(x_proj_w, w_xp, 96 * I_ / 4);      // 3
    to_half_kernel<<<128, 256>>>(dt_proj_w, w_dt, I_ * R_ / 4);     // 4
    to_half_kernel<<<2048, 256>>>(out_proj_w, w_out, H_ * I_ / 4);  // 5
    // 6: proj_h = h @ in_proj^T   (16384 x 4096 x 1024)
    hgemm<<<dim3(32, 128), 256, GEMM_SMEM>>>(h, H_, w_in, nullptr, nullptr,
                                             nullptr, proj_h, 4096, H_, 0, 4096);
    conv_silu_kernel<<<BT_ * 512 / 256, 256>>>(proj_h, conv_w, conv_b, xi);
    // sp = xi @ x_proj^T     (16384 x 96 x 2048), fp32 + half out
    hgemm<<<dim3(1, 128), 256, GEMM_SMEM>>>(xi, I_, w_xp, nullptr, nullptr, sp,
                                            sp_h, 96, I_, 0, 96);
    // dt = softplus(sp[:,:64] @ dt_proj^T + b)   (16384 x 2048 x 64)
    hgemm<<<dim3(16, 128), 256, GEMM_SMEM>>>(sp_h, 96, w_dt, dt_proj_b, nullptr,
                                             dt, nullptr, I_, R_, 1, I_);
    // scan -> yraw (half)
    scan_kernel<<<(B_ * I_) / 32, 256>>>(dt, sp, xi, A_log, yraw);
    // y_h = half((yraw + xi*D) * silu(gate))
    ypost_kernel<<<BT_ * 512 / 256, 256>>>(yraw, xi, Dv, proj_h, y_h);
    // x2 = x + y @ out_proj^T   (16384 x 1024 x 2048)
    hgemm<<<dim3(8, 128), 256, GEMM_SMEM>>>(y_h, I_, w_out, x, nullptr, x2,
                                            nullptr, H_, I_, 2, H_);
    rmsnorm_kernel<<<BT_, 256>>>(x2, mlp_norm_w, h);
    to_half_kernel<<<2816, 256>>>(gate_w, w_gate, M_MLP * H_ / 4);
    to_half_kernel<<<2816, 256>>>(up_w, w_up, M_MLP * H_ / 4);
    to_half_kernel<<<2816, 256>>>(down_w, w_down, H_ * M_MLP / 4);
    // gate(half) = h @ gate_w^T   (16384 x 2816 x 1024)
    hgemm<<<dim3(22, 128), 256, GEMM_SMEM>>>(h, H_, w_gate, nullptr, nullptr,
                                             nullptr, proj_h, M_MLP, H_, 0,
                                             M_MLP);
    // act = half(silu(gate) * (h @ up_w^T))
    hgemm<<<dim3(22, 128), 256, GEMM_SMEM>>>(h, H_, w_up, nullptr, proj_h,
                                             nullptr, act, M_MLP, H_, 3, M_MLP);
    // out = x2 + act @ down_w^T   (16384 x 1024 x 2816)
    hgemm<<<dim3(8, 128), 256, GEMM_SMEM>>>(act, M_MLP, w_down, x2, nullptr,
                                            out, nullptr, H_, M_MLP, 2, H_);
}